// round 3
// baseline (speedup 1.0000x reference)
#include <cuda_runtime.h>
#include <math.h>

#define SQL 48
#define BB  128
#define HDIM 100
#define LDX 1116   // max concatenated feature width (layer-5 input)

// ------------------------- scratch (device globals; no allocs) -------------
__device__ float g_PX[SQL*BB*LDX];     // query stream features [S][B][LDX]
__device__ float g_HX[SQL*BB*LDX];     // support stream features
__device__ float g_GP[SQL*BB*400];     // precomputed x@wih^T + biases (query)
__device__ float g_GH[SQL*BB*400];     // (support)
__device__ float g_PH[SQL*BB*HDIM];    // current layer hidden states (query)
__device__ float g_HHs[SQL*BB*HDIM];   // (support)

// ------------------------- embedding + char conv ---------------------------
__global__ __launch_bounds__(128) void embed_kernel(
    const int* __restrict__ words, const int* __restrict__ chars,
    const float* __restrict__ word_emb, const float* __restrict__ char_emb,
    const float* __restrict__ conv_w, const float* __restrict__ conv_b,
    int which)
{
    float* X = which ? g_HX : g_PX;
    int m = blockIdx.x;       // 0..6143
    int b = m / SQL;
    int s = m % SQL;
    int tid = threadIdx.x;    // 128 threads

    __shared__ float ce[256];
    __shared__ float wsh[48];
    __shared__ float cb[16];
    if (tid < 48) wsh[tid] = conv_w[tid];
    if (tid < 16) cb[tid]  = conv_b[tid];

    // char embedding flatten: j = c*16 + d
    for (int idx = tid; idx < 256; idx += 128) {
        int c = idx >> 4, dd = idx & 15;
        int ch = chars[(b*SQL + s)*16 + c];
        ce[idx] = char_emb[ch*16 + dd];
    }
    // word embedding copy
    int w = words[b*SQL + s];
    int row = s*BB + b;
    for (int i = tid; i < 300; i += 128)
        X[row*LDX + i] = word_emb[w*300 + i];
    __syncthreads();

    // conv1d K=3 VALID over the flattened 256, per output channel o; max-pool
    int o = tid >> 3, l = tid & 7;
    float w0 = wsh[o*3], w1 = wsh[o*3+1], w2 = wsh[o*3+2];
    float mx = -1e30f;
    for (int t = l; t < 254; t += 8) {
        float v = ce[t]*w0 + ce[t+1]*w1 + ce[t+2]*w2;
        mx = fmaxf(mx, v);
    }
    #pragma unroll
    for (int off = 4; off; off >>= 1)
        mx = fmaxf(mx, __shfl_down_sync(0xffffffffu, mx, off, 8));
    if (l == 0) {
        float v = mx + cb[o];
        if (b != 0) v = fmaxf(v, 0.f);   // reference quirk: batch row 0 skips relu
        X[row*LDX + 300 + o] = v;
    }
}

// ------------------------- wih GEMM: Y = X @ W^T + (bih+bhh) ---------------
// X: [6144, d] with ld=LDX; W: [400, d]; Y: [6144, 400]
// BM=128, BN=64, BK=16, 256 thr, TM=8, TN=4
__global__ __launch_bounds__(256) void gemm_wih(
    const float* __restrict__ W, const float* __restrict__ bih,
    const float* __restrict__ bhh, int d)
{
    const float* X = blockIdx.z ? g_HX : g_PX;
    float* Y       = blockIdx.z ? g_GH : g_GP;
    __shared__ float As[16][128];
    __shared__ float Bs[16][64];

    int tid = threadIdx.x;
    int tx = tid & 15, ty = tid >> 4;
    int m0 = blockIdx.y * 128;
    int n0 = blockIdx.x * 64;

    float acc[8][4];
    #pragma unroll
    for (int i = 0; i < 8; i++)
        #pragma unroll
        for (int j = 0; j < 4; j++) acc[i][j] = 0.f;

    int arow = tid >> 2;           // 0..63
    int akq  = (tid & 3) * 4;      // k sub-offset (d is always a multiple of 4)
    int nK = (d + 15) >> 4;

    for (int kt = 0; kt < nK; kt++) {
        int k0 = kt << 4;
        #pragma unroll
        for (int r = 0; r < 2; r++) {
            int rw = arow + r*64;
            float4 v = make_float4(0.f,0.f,0.f,0.f);
            if (k0 + akq < d)
                v = *reinterpret_cast<const float4*>(&X[(size_t)(m0+rw)*LDX + k0 + akq]);
            As[akq+0][rw] = v.x; As[akq+1][rw] = v.y;
            As[akq+2][rw] = v.z; As[akq+3][rw] = v.w;
        }
        {
            int n = n0 + arow;
            float4 v = make_float4(0.f,0.f,0.f,0.f);
            if (n < 400 && k0 + akq < d)
                v = *reinterpret_cast<const float4*>(&W[(size_t)n*d + k0 + akq]);
            Bs[akq+0][arow] = v.x; Bs[akq+1][arow] = v.y;
            Bs[akq+2][arow] = v.z; Bs[akq+3][arow] = v.w;
        }
        __syncthreads();
        #pragma unroll
        for (int k = 0; k < 16; k++) {
            float4 a0 = *reinterpret_cast<const float4*>(&As[k][ty*8]);
            float4 a1 = *reinterpret_cast<const float4*>(&As[k][ty*8+4]);
            float4 bv = *reinterpret_cast<const float4*>(&Bs[k][tx*4]);
            float a[8] = {a0.x,a0.y,a0.z,a0.w,a1.x,a1.y,a1.z,a1.w};
            float bb4[4] = {bv.x,bv.y,bv.z,bv.w};
            #pragma unroll
            for (int i = 0; i < 8; i++)
                #pragma unroll
                for (int j = 0; j < 4; j++)
                    acc[i][j] += a[i]*bb4[j];
        }
        __syncthreads();
    }
    #pragma unroll
    for (int i = 0; i < 8; i++) {
        int m = m0 + ty*8 + i;
        #pragma unroll
        for (int j = 0; j < 4; j++) {
            int n = n0 + tx*4 + j;
            if (n < 400)
                Y[(size_t)m*400 + n] = acc[i][j] + bih[n] + bhh[n];
        }
    }
}

// ------------------------- LSTM recurrence ---------------------------------
// One block per (sequence, batch element). whh lives in registers:
// thread (j = tid%100, part = tid/100, part<5) owns whh[{q*100+j}][part*20 .. +19]
__device__ __forceinline__ float sigmf(float x) { return 1.f/(1.f+expf(-x)); }

__global__ __launch_bounds__(512) void lstm_kernel(
    const float* __restrict__ whh, int dk, int writeX)
{
    int blk = blockIdx.x;
    int seq = blk >> 7;
    int b   = blk & 127;
    const float* G = seq ? g_GH : g_GP;
    float* Hout    = seq ? g_HHs : g_PH;
    float* Xout    = seq ? g_HX  : g_PX;

    int tid = threadIdx.x;
    __shared__ float  h_s[100];
    __shared__ float4 ps4[5][100];

    int j = tid % 100;
    int part = tid / 100;
    float w[4][20];
    if (tid < 500) {
        #pragma unroll
        for (int q = 0; q < 4; q++)
            #pragma unroll
            for (int ii = 0; ii < 20; ii++)
                w[q][ii] = whh[(q*100 + j)*100 + part*20 + ii];
    }
    float c = 0.f;
    if (tid < 100) h_s[tid] = 0.f;
    __syncthreads();

    for (int t = 0; t < 48; t++) {
        if (tid < 500) {
            float4 a = make_float4(0.f,0.f,0.f,0.f);
            int base = part*20;
            #pragma unroll
            for (int ii = 0; ii < 20; ii++) {
                float hv = h_s[base+ii];
                a.x += hv*w[0][ii];
                a.y += hv*w[1][ii];
                a.z += hv*w[2][ii];
                a.w += hv*w[3][ii];
            }
            ps4[part][j] = a;
        }
        __syncthreads();
        if (tid < 100) {
            const float* g0 = G + (size_t)(t*128 + b)*400;
            float gi = g0[tid], gf = g0[100+tid], gg = g0[200+tid], go = g0[300+tid];
            #pragma unroll
            for (int p = 0; p < 5; p++) {
                float4 v = ps4[p][tid];
                gi += v.x; gf += v.y; gg += v.z; go += v.w;
            }
            c = sigmf(gf)*c + sigmf(gi)*tanhf(gg);
            float h = sigmf(go)*tanhf(c);
            h_s[tid] = h;
            Hout[(size_t)(t*128+b)*100 + tid] = h;
            if (writeX)
                Xout[(size_t)(t*128+b)*LDX + dk + 100 + tid] = h;
        }
        __syncthreads();
    }
}

// ------------------------- cross attention ---------------------------------
// per batch b: attn = hp @ hh^T [48,48]; a_p = softmax_rows(attn) @ hh;
// a_h = softmax_cols(attn)^T-weighted @ hp. Written into PX/HX cols [dk, dk+100).
__global__ __launch_bounds__(256) void attn_kernel(int dk)
{
    extern __shared__ float smem[];
    float* hp   = smem;            // 4800
    float* hh   = smem + 4800;     // 4800
    float* attn = smem + 9600;     // 2304
    float* E    = smem + 11904;    // 2304
    float* rmax = smem + 14208;    // 48
    float* rsum = rmax + 48;
    float* cmax = rsum + 48;
    float* csum = cmax + 48;

    int b = blockIdx.x;
    int tid = threadIdx.x;

    for (int idx = tid; idx < 4800; idx += 256) {
        int s = idx / 100, h2 = idx % 100;
        hp[idx] = g_PH [(size_t)(s*128+b)*100 + h2];
        hh[idx] = g_HHs[(size_t)(s*128+b)*100 + h2];
    }
    __syncthreads();

    for (int idx = tid; idx < 2304; idx += 256) {
        int p = idx / 48, q = idx % 48;
        const float* hpp = hp + p*100;
        const float* hhq = hh + q*100;
        float a = 0.f;
        #pragma unroll 4
        for (int i = 0; i < 100; i++) a += hpp[i]*hhq[i];
        attn[idx] = a;
    }
    __syncthreads();

    if (tid < 48) {
        float m = -1e30f;
        for (int q = 0; q < 48; q++) m = fmaxf(m, attn[tid*48+q]);
        float s2 = 0.f;
        for (int q = 0; q < 48; q++) s2 += expf(attn[tid*48+q]-m);
        rmax[tid] = m; rsum[tid] = s2;
    } else if (tid >= 128 && tid < 176) {
        int q = tid - 128;
        float m = -1e30f;
        for (int p = 0; p < 48; p++) m = fmaxf(m, attn[p*48+q]);
        float s2 = 0.f;
        for (int p = 0; p < 48; p++) s2 += expf(attn[p*48+q]-m);
        cmax[q] = m; csum[q] = s2;
    }
    __syncthreads();

    // a_p: row softmax @ hh
    for (int idx = tid; idx < 2304; idx += 256) {
        int p = idx / 48;
        E[idx] = expf(attn[idx]-rmax[p]) / rsum[p];
    }
    __syncthreads();
    for (int idx = tid; idx < 4800; idx += 256) {
        int p = idx / 100, h2 = idx % 100;
        float a = 0.f;
        #pragma unroll 4
        for (int q = 0; q < 48; q++) a += E[p*48+q]*hh[q*100+h2];
        g_PX[(size_t)(p*128+b)*LDX + dk + h2] = a;
    }
    __syncthreads();

    // a_h: column softmax @ hp
    for (int idx = tid; idx < 2304; idx += 256) {
        int q = idx % 48;
        E[idx] = expf(attn[idx]-cmax[q]) / csum[q];
    }
    __syncthreads();
    for (int idx = tid; idx < 4800; idx += 256) {
        int q = idx / 100, h2 = idx % 100;
        float a = 0.f;
        #pragma unroll 4
        for (int p = 0; p < 48; p++) a += E[p*48+q]*hp[p*100+h2];
        g_HX[(size_t)(q*128+b)*LDX + dk + h2] = a;
    }
}

// ------------------------- pooling + FC head -------------------------------
__global__ __launch_bounds__(256) void head_kernel(
    const float* __restrict__ fcl_w, const float* __restrict__ fcl_b,
    const float* __restrict__ last_w, const float* __restrict__ last_b,
    float* __restrict__ out)
{
    __shared__ float feats[500];
    __shared__ float o1[800];
    __shared__ float red[256];
    int b = blockIdx.x, tid = threadIdx.x;

    if (tid < 100) {
        float hq = -1e30f, hs = -1e30f;
        for (int s = 0; s < 48; s++) {
            hq = fmaxf(hq, g_PH [(size_t)(s*128+b)*100 + tid]);
            hs = fmaxf(hs, g_HHs[(size_t)(s*128+b)*100 + tid]);
        }
        feats[tid]       = hq;
        feats[100 + tid] = hs;
        feats[200 + tid] = hs - hq;
        feats[300 + tid] = hq * hs;
        feats[400 + tid] = fabsf(hq - hs);
    }
    __syncthreads();

    for (int o = tid; o < 800; o += 256) {
        float a = fcl_b[o];
        const float* wr = fcl_w + (size_t)o*500;
        #pragma unroll 4
        for (int k = 0; k < 500; k++) a += feats[k]*wr[k];
        o1[o] = fmaxf(a, 0.f);
    }
    __syncthreads();

    for (int cc = 0; cc < 2; cc++) {
        float pa = 0.f;
        for (int o = tid; o < 800; o += 256) pa += o1[o]*last_w[cc*800+o];
        red[tid] = pa;
        __syncthreads();
        for (int off = 128; off; off >>= 1) {
            if (tid < off) red[tid] += red[tid+off];
            __syncthreads();
        }
        if (tid == 0) {
            float v = red[0] + last_b[cc];
            out[b*2+cc] = 1.f/(1.f+expf(-v));
        }
        __syncthreads();
    }
}

// ------------------------- launch ------------------------------------------
extern "C" void kernel_launch(void* const* d_in, const int* in_sizes, int n_in,
                              void* d_out, int out_size)
{
    const int*   q_words  = (const int*)d_in[0];
    const int*   q_chars  = (const int*)d_in[1];
    const int*   s_words  = (const int*)d_in[2];
    const int*   s_chars  = (const int*)d_in[3];
    const float* word_emb = (const float*)d_in[4];
    const float* char_emb = (const float*)d_in[5];
    const float* conv_w   = (const float*)d_in[6];
    const float* conv_b   = (const float*)d_in[7];
    const float* fcl_w    = (const float*)d_in[28];
    const float* fcl_b    = (const float*)d_in[29];
    const float* last_w   = (const float*)d_in[30];
    const float* last_b   = (const float*)d_in[31];
    float* out = (float*)d_out;

    cudaFuncSetAttribute(attn_kernel, cudaFuncAttributeMaxDynamicSharedMemorySize, 57600);

    embed_kernel<<<6144,128>>>(q_words, q_chars, word_emb, char_emb, conv_w, conv_b, 0);
    embed_kernel<<<6144,128>>>(s_words, s_chars, word_emb, char_emb, conv_w, conv_b, 1);

    const int dims[5] = {316, 516, 716, 916, 1116};
    for (int k = 0; k < 5; k++) {
        const float* wih = (const float*)d_in[8+4*k];
        const float* whh = (const float*)d_in[9+4*k];
        const float* bih = (const float*)d_in[10+4*k];
        const float* bhh = (const float*)d_in[11+4*k];
        dim3 gg(7, 48, 2);
        gemm_wih<<<gg, 256>>>(wih, bih, bhh, dims[k]);
        lstm_kernel<<<256, 512>>>(whh, dims[k], (k < 4) ? 1 : 0);
        if (k < 4) attn_kernel<<<128, 256, 57600>>>(dims[k]);
    }
    head_kernel<<<128, 256>>>(fcl_w, fcl_b, last_w, last_b, out);
}

// round 4
// speedup vs baseline: 1.2499x; 1.2499x over previous
#include <cuda_runtime.h>
#include <math.h>
#include <stdint.h>

#define SQL 48
#define BB  128
#define HDIM 100
#define LDX 1116   // max concatenated feature width (layer-5 input)

// ------------------------- scratch (device globals; no allocs) -------------
__device__ float g_PX[SQL*BB*LDX];     // query stream features [S][B][LDX]
__device__ float g_HX[SQL*BB*LDX];     // support stream features
__device__ float g_GP[SQL*BB*400];     // precomputed x@wih^T + biases (query)
__device__ float g_GH[SQL*BB*400];     // (support)
__device__ float g_PH[SQL*BB*HDIM];    // current layer hidden states (query)
__device__ float g_HHs[SQL*BB*HDIM];   // (support)

// ------------------------- embedding + char conv ---------------------------
__global__ __launch_bounds__(128) void embed_kernel(
    const int* __restrict__ words, const int* __restrict__ chars,
    const float* __restrict__ word_emb, const float* __restrict__ char_emb,
    const float* __restrict__ conv_w, const float* __restrict__ conv_b,
    int which)
{
    float* X = which ? g_HX : g_PX;
    int m = blockIdx.x;       // 0..6143
    int b = m / SQL;
    int s = m % SQL;
    int tid = threadIdx.x;    // 128 threads

    __shared__ float ce[256];
    __shared__ float wsh[48];
    __shared__ float cb[16];
    if (tid < 48) wsh[tid] = conv_w[tid];
    if (tid < 16) cb[tid]  = conv_b[tid];

    for (int idx = tid; idx < 256; idx += 128) {
        int c = idx >> 4, dd = idx & 15;
        int ch = chars[(b*SQL + s)*16 + c];
        ce[idx] = char_emb[ch*16 + dd];
    }
    int w = words[b*SQL + s];
    int row = s*BB + b;
    for (int i = tid; i < 300; i += 128)
        X[row*LDX + i] = word_emb[w*300 + i];
    __syncthreads();

    int o = tid >> 3, l = tid & 7;
    float w0 = wsh[o*3], w1 = wsh[o*3+1], w2 = wsh[o*3+2];
    float mx = -1e30f;
    for (int t = l; t < 254; t += 8) {
        float v = ce[t]*w0 + ce[t+1]*w1 + ce[t+2]*w2;
        mx = fmaxf(mx, v);
    }
    #pragma unroll
    for (int off = 4; off; off >>= 1)
        mx = fmaxf(mx, __shfl_down_sync(0xffffffffu, mx, off, 8));
    if (l == 0) {
        float v = mx + cb[o];
        if (b != 0) v = fmaxf(v, 0.f);   // reference quirk: batch row 0 skips relu
        X[row*LDX + 300 + o] = v;
    }
}

// ------------------------- tf32 tensor-core GEMM ---------------------------
// Y = X @ W^T + (bih+bhh); X: [6144, d] ld=LDX; W: [400, d]; Y: [6144, 400]
// BM=128, BN=64, BK=32; 8 warps, warp tile 32x32 via mma.m16n8k8 tf32.
__device__ __forceinline__ float to_tf32(float x) {
    float y;
    asm("cvt.rna.tf32.f32 %0, %1;" : "=f"(y) : "f"(x));
    return y;
}

__device__ __forceinline__ void mma_tf32(float* c, const uint32_t* a, const uint32_t* b) {
    asm volatile(
        "mma.sync.aligned.m16n8k8.row.col.f32.tf32.tf32.f32 "
        "{%0,%1,%2,%3}, {%4,%5,%6,%7}, {%8,%9}, {%0,%1,%2,%3};"
        : "+f"(c[0]), "+f"(c[1]), "+f"(c[2]), "+f"(c[3])
        : "r"(a[0]), "r"(a[1]), "r"(a[2]), "r"(a[3]), "r"(b[0]), "r"(b[1]));
}

#define APAD 36

__global__ __launch_bounds__(256) void gemm_wih_tc(
    const float* __restrict__ W, const float* __restrict__ bih,
    const float* __restrict__ bhh, int d)
{
    const float* X = blockIdx.z ? g_HX : g_PX;
    float* Y       = blockIdx.z ? g_GH : g_GP;
    __shared__ float As[128][APAD];   // 18 KB (tf32 bit patterns)
    __shared__ float Bs[64][APAD];    //  9 KB

    int tid  = threadIdx.x;
    int wid  = tid >> 5, lane = tid & 31;
    int wm   = wid >> 1, wn = wid & 1;       // warp tile: rows 32*wm, cols 32*wn
    int m0   = blockIdx.y * 128;
    int n0   = blockIdx.x * 64;
    int lg   = lane >> 2;                    // 0..7
    int lk   = lane & 3;                     // 0..3

    float acc[2][4][4];
    #pragma unroll
    for (int i = 0; i < 2; i++)
        #pragma unroll
        for (int j = 0; j < 4; j++)
            #pragma unroll
            for (int r = 0; r < 4; r++) acc[i][j][r] = 0.f;

    int nChunk = (d + 31) >> 5;
    for (int kc = 0; kc < nChunk; kc++) {
        int k0 = kc << 5;
        // A tile: 128 rows x 32 k = 1024 float4, 4 per thread
        #pragma unroll
        for (int i = 0; i < 4; i++) {
            int idx = tid + 256*i;
            int rm = idx >> 3, rk = (idx & 7) << 2;
            float4 v = make_float4(0.f,0.f,0.f,0.f);
            if (k0 + rk < d)
                v = *reinterpret_cast<const float4*>(&X[(size_t)(m0+rm)*LDX + k0 + rk]);
            v.x = to_tf32(v.x); v.y = to_tf32(v.y);
            v.z = to_tf32(v.z); v.w = to_tf32(v.w);
            *reinterpret_cast<float4*>(&As[rm][rk]) = v;
        }
        // B tile: 64 rows x 32 k = 512 float4, 2 per thread
        #pragma unroll
        for (int i = 0; i < 2; i++) {
            int idx = tid + 256*i;
            int rn = idx >> 3, rk = (idx & 7) << 2;
            float4 v = make_float4(0.f,0.f,0.f,0.f);
            if (n0 + rn < 400 && k0 + rk < d)
                v = *reinterpret_cast<const float4*>(&W[(size_t)(n0+rn)*d + k0 + rk]);
            v.x = to_tf32(v.x); v.y = to_tf32(v.y);
            v.z = to_tf32(v.z); v.w = to_tf32(v.w);
            *reinterpret_cast<float4*>(&Bs[rn][rk]) = v;
        }
        __syncthreads();

        #pragma unroll
        for (int ks = 0; ks < 4; ks++) {
            int kk = ks*8 + lk;
            uint32_t a[2][4], b[4][2];
            #pragma unroll
            for (int mt = 0; mt < 2; mt++) {
                int mr = wm*32 + mt*16 + lg;
                a[mt][0] = __float_as_uint(As[mr  ][kk  ]);
                a[mt][1] = __float_as_uint(As[mr+8][kk  ]);
                a[mt][2] = __float_as_uint(As[mr  ][kk+4]);
                a[mt][3] = __float_as_uint(As[mr+8][kk+4]);
            }
            #pragma unroll
            for (int nt = 0; nt < 4; nt++) {
                int nr = wn*32 + nt*8 + lg;
                b[nt][0] = __float_as_uint(Bs[nr][kk  ]);
                b[nt][1] = __float_as_uint(Bs[nr][kk+4]);
            }
            #pragma unroll
            for (int mt = 0; mt < 2; mt++)
                #pragma unroll
                for (int nt = 0; nt < 4; nt++)
                    mma_tf32(acc[mt][nt], a[mt], b[nt]);
        }
        __syncthreads();
    }

    // epilogue (400 % 8 == 0 so an n8 tile is wholly in or out)
    #pragma unroll
    for (int mt = 0; mt < 2; mt++) {
        int row0 = m0 + wm*32 + mt*16 + lg;
        #pragma unroll
        for (int nt = 0; nt < 4; nt++) {
            int col0 = n0 + wn*32 + nt*8 + 2*lk;
            if (col0 < 400) {
                float bs0 = bih[col0]   + bhh[col0];
                float bs1 = bih[col0+1] + bhh[col0+1];
                Y[(size_t)row0*400 + col0]       = acc[mt][nt][0] + bs0;
                Y[(size_t)row0*400 + col0+1]     = acc[mt][nt][1] + bs1;
                Y[(size_t)(row0+8)*400 + col0]   = acc[mt][nt][2] + bs0;
                Y[(size_t)(row0+8)*400 + col0+1] = acc[mt][nt][3] + bs1;
            }
        }
    }
}

// ------------------------- LSTM recurrence ---------------------------------
// 128 blocks (single wave): block handles (seq, b) and (seq, b+64).
// whh in registers (thread part/j owns whh[q*100+j][part*20..+19], reused for
// both batch elements). Gate vectors for t+1 prefetched during step t.
__device__ __forceinline__ float sigmf(float x) { return 1.f/(1.f+__expf(-x)); }
__device__ __forceinline__ float tanhf_fast(float x) { return 1.f - 2.f/(__expf(2.f*x)+1.f); }

__global__ __launch_bounds__(512) void lstm_kernel(
    const float* __restrict__ whh, int dk, int writeX)
{
    int blk = blockIdx.x;        // 0..127
    int seq = blk >> 6;
    int bp  = blk & 63;
    const float* G = seq ? g_GH : g_GP;
    float* Hout    = seq ? g_HHs : g_PH;
    float* Xout    = seq ? g_HX  : g_PX;
    int bA = bp, bB = bp + 64;

    int tid  = threadIdx.x;
    int j    = tid % 100;
    int part = tid / 100;        // 0..5

    __shared__ float  h_s[2][100];
    __shared__ float4 ps4[2][5][100];
    __shared__ float  gcur[2][400];

    float w[4][20];
    if (tid < 500) {
        #pragma unroll
        for (int q = 0; q < 4; q++)
            #pragma unroll
            for (int ii = 0; ii < 20; ii++)
                w[q][ii] = whh[(q*100 + j)*100 + part*20 + ii];
    }

    float ga = 0.f, gb = 0.f;
    if (tid < 400) {
        ga = G[(size_t)bA*400 + tid];
        gb = G[(size_t)bB*400 + tid];
    }
    float c = 0.f;
    if (tid < 100) { h_s[0][tid] = 0.f; h_s[1][tid] = 0.f; }
    __syncthreads();

    for (int t = 0; t < 48; t++) {
        if (tid < 400) { gcur[0][tid] = ga; gcur[1][tid] = gb; }
        if (tid < 500) {
            float4 aa = make_float4(0.f,0.f,0.f,0.f);
            float4 ab = make_float4(0.f,0.f,0.f,0.f);
            int base = part*20;
            #pragma unroll
            for (int ii = 0; ii < 20; ii++) {
                float ha = h_s[0][base+ii];
                float hb = h_s[1][base+ii];
                aa.x += ha*w[0][ii]; aa.y += ha*w[1][ii];
                aa.z += ha*w[2][ii]; aa.w += ha*w[3][ii];
                ab.x += hb*w[0][ii]; ab.y += hb*w[1][ii];
                ab.z += hb*w[2][ii]; ab.w += hb*w[3][ii];
            }
            ps4[0][part][j] = aa;
            ps4[1][part][j] = ab;
        }
        if (t+1 < 48 && tid < 400) {   // prefetch next step's gates (hidden by this step)
            ga = G[(size_t)((t+1)*128 + bA)*400 + tid];
            gb = G[(size_t)((t+1)*128 + bB)*400 + tid];
        }
        __syncthreads();
        if (tid < 200) {               // part == bi here (0 or 1)
            int bi = part;
            float gi = gcur[bi][j],     gf = gcur[bi][100+j];
            float gg = gcur[bi][200+j], go = gcur[bi][300+j];
            #pragma unroll
            for (int p = 0; p < 5; p++) {
                float4 v = ps4[bi][p][j];
                gi += v.x; gf += v.y; gg += v.z; go += v.w;
            }
            c = sigmf(gf)*c + sigmf(gi)*tanhf_fast(gg);
            float h = sigmf(go)*tanhf_fast(c);
            h_s[bi][j] = h;
            int b = bi ? bB : bA;
            Hout[(size_t)(t*128+b)*100 + j] = h;
            if (writeX)
                Xout[(size_t)(t*128+b)*LDX + dk + 100 + j] = h;
        }
        __syncthreads();
    }
}

// ------------------------- cross attention ---------------------------------
__global__ __launch_bounds__(256) void attn_kernel(int dk)
{
    extern __shared__ float smem[];
    float* hp   = smem;            // 4800
    float* hh   = smem + 4800;     // 4800
    float* attn = smem + 9600;     // 2304
    float* E    = smem + 11904;    // 2304
    float* rmax = smem + 14208;    // 48
    float* rsum = rmax + 48;
    float* cmax = rsum + 48;
    float* csum = cmax + 48;

    int b = blockIdx.x;
    int tid = threadIdx.x;

    for (int idx = tid; idx < 4800; idx += 256) {
        int s = idx / 100, h2 = idx % 100;
        hp[idx] = g_PH [(size_t)(s*128+b)*100 + h2];
        hh[idx] = g_HHs[(size_t)(s*128+b)*100 + h2];
    }
    __syncthreads();

    for (int idx = tid; idx < 2304; idx += 256) {
        int p = idx / 48, q = idx % 48;
        const float* hpp = hp + p*100;
        const float* hhq = hh + q*100;
        float a = 0.f;
        #pragma unroll 4
        for (int i = 0; i < 100; i++) a += hpp[i]*hhq[i];
        attn[idx] = a;
    }
    __syncthreads();

    if (tid < 48) {
        float m = -1e30f;
        for (int q = 0; q < 48; q++) m = fmaxf(m, attn[tid*48+q]);
        float s2 = 0.f;
        for (int q = 0; q < 48; q++) s2 += expf(attn[tid*48+q]-m);
        rmax[tid] = m; rsum[tid] = s2;
    } else if (tid >= 128 && tid < 176) {
        int q = tid - 128;
        float m = -1e30f;
        for (int p = 0; p < 48; p++) m = fmaxf(m, attn[p*48+q]);
        float s2 = 0.f;
        for (int p = 0; p < 48; p++) s2 += expf(attn[p*48+q]-m);
        cmax[q] = m; csum[q] = s2;
    }
    __syncthreads();

    for (int idx = tid; idx < 2304; idx += 256) {
        int p = idx / 48;
        E[idx] = expf(attn[idx]-rmax[p]) / rsum[p];
    }
    __syncthreads();
    for (int idx = tid; idx < 4800; idx += 256) {
        int p = idx / 100, h2 = idx % 100;
        float a = 0.f;
        #pragma unroll 4
        for (int q = 0; q < 48; q++) a += E[p*48+q]*hh[q*100+h2];
        g_PX[(size_t)(p*128+b)*LDX + dk + h2] = a;
    }
    __syncthreads();

    for (int idx = tid; idx < 2304; idx += 256) {
        int q = idx % 48;
        E[idx] = expf(attn[idx]-cmax[q]) / csum[q];
    }
    __syncthreads();
    for (int idx = tid; idx < 4800; idx += 256) {
        int q = idx / 100, h2 = idx % 100;
        float a = 0.f;
        #pragma unroll 4
        for (int p = 0; p < 48; p++) a += E[p*48+q]*hp[p*100+h2];
        g_HX[(size_t)(q*128+b)*LDX + dk + h2] = a;
    }
}

// ------------------------- pooling + FC head -------------------------------
__global__ __launch_bounds__(256) void head_kernel(
    const float* __restrict__ fcl_w, const float* __restrict__ fcl_b,
    const float* __restrict__ last_w, const float* __restrict__ last_b,
    float* __restrict__ out)
{
    __shared__ float feats[500];
    __shared__ float o1[800];
    __shared__ float red[256];
    int b = blockIdx.x, tid = threadIdx.x;

    if (tid < 100) {
        float hq = -1e30f, hs = -1e30f;
        for (int s = 0; s < 48; s++) {
            hq = fmaxf(hq, g_PH [(size_t)(s*128+b)*100 + tid]);
            hs = fmaxf(hs, g_HHs[(size_t)(s*128+b)*100 + tid]);
        }
        feats[tid]       = hq;
        feats[100 + tid] = hs;
        feats[200 + tid] = hs - hq;
        feats[300 + tid] = hq * hs;
        feats[400 + tid] = fabsf(hq - hs);
    }
    __syncthreads();

    for (int o = tid; o < 800; o += 256) {
        float a = fcl_b[o];
        const float* wr = fcl_w + (size_t)o*500;
        #pragma unroll 4
        for (int k = 0; k < 500; k++) a += feats[k]*wr[k];
        o1[o] = fmaxf(a, 0.f);
    }
    __syncthreads();

    for (int cc = 0; cc < 2; cc++) {
        float pa = 0.f;
        for (int o = tid; o < 800; o += 256) pa += o1[o]*last_w[cc*800+o];
        red[tid] = pa;
        __syncthreads();
        for (int off = 128; off; off >>= 1) {
            if (tid < off) red[tid] += red[tid+off];
            __syncthreads();
        }
        if (tid == 0) {
            float v = red[0] + last_b[cc];
            out[b*2+cc] = 1.f/(1.f+expf(-v));
        }
        __syncthreads();
    }
}

// ------------------------- launch ------------------------------------------
extern "C" void kernel_launch(void* const* d_in, const int* in_sizes, int n_in,
                              void* d_out, int out_size)
{
    const int*   q_words  = (const int*)d_in[0];
    const int*   q_chars  = (const int*)d_in[1];
    const int*   s_words  = (const int*)d_in[2];
    const int*   s_chars  = (const int*)d_in[3];
    const float* word_emb = (const float*)d_in[4];
    const float* char_emb = (const float*)d_in[5];
    const float* conv_w   = (const float*)d_in[6];
    const float* conv_b   = (const float*)d_in[7];
    const float* fcl_w    = (const float*)d_in[28];
    const float* fcl_b    = (const float*)d_in[29];
    const float* last_w   = (const float*)d_in[30];
    const float* last_b   = (const float*)d_in[31];
    float* out = (float*)d_out;

    cudaFuncSetAttribute(attn_kernel, cudaFuncAttributeMaxDynamicSharedMemorySize, 57600);

    embed_kernel<<<6144,128>>>(q_words, q_chars, word_emb, char_emb, conv_w, conv_b, 0);
    embed_kernel<<<6144,128>>>(s_words, s_chars, word_emb, char_emb, conv_w, conv_b, 1);

    const int dims[5] = {316, 516, 716, 916, 1116};
    for (int k = 0; k < 5; k++) {
        const float* wih = (const float*)d_in[8+4*k];
        const float* whh = (const float*)d_in[9+4*k];
        const float* bih = (const float*)d_in[10+4*k];
        const float* bhh = (const float*)d_in[11+4*k];
        dim3 gg(7, 48, 2);
        gemm_wih_tc<<<gg, 256>>>(wih, bih, bhh, dims[k]);
        lstm_kernel<<<128, 512>>>(whh, dims[k], (k < 4) ? 1 : 0);
        if (k < 4) attn_kernel<<<128, 256, 57600>>>(dims[k]);
    }
    head_kernel<<<128, 256>>>(fcl_w, fcl_b, last_w, last_b, out);
}

// round 5
// speedup vs baseline: 1.2945x; 1.0357x over previous
#include <cuda_runtime.h>
#include <cuda_bf16.h>
#include <math.h>
#include <stdint.h>

#define SQL 48
#define BB  128
#define HDIM 100
#define LDXP 1120   // padded feature width (bf16 rows, 16B-aligned)

// ------------------------- scratch (device globals; no allocs) -------------
__device__ __nv_bfloat16 g_PX[SQL*BB*LDXP];  // query features (bf16, gemm input)
__device__ __nv_bfloat16 g_HX[SQL*BB*LDXP];  // support features
__device__ float g_GP[SQL*BB*400];           // x@wih^T + biases (query)
__device__ float g_GH[SQL*BB*400];           // (support)
__device__ float g_PH[SQL*BB*HDIM];          // hidden states (query, fp32)
__device__ float g_HHs[SQL*BB*HDIM];         // (support)

// ------------------------- embedding + char conv ---------------------------
__global__ __launch_bounds__(128) void embed_kernel(
    const int* __restrict__ words, const int* __restrict__ chars,
    const float* __restrict__ word_emb, const float* __restrict__ char_emb,
    const float* __restrict__ conv_w, const float* __restrict__ conv_b,
    int which)
{
    __nv_bfloat16* X = which ? g_HX : g_PX;
    int m = blockIdx.x;       // 0..6143
    int b = m / SQL;
    int s = m % SQL;
    int tid = threadIdx.x;

    __shared__ float ce[256];
    __shared__ float wsh[48];
    __shared__ float cb[16];
    if (tid < 48) wsh[tid] = conv_w[tid];
    if (tid < 16) cb[tid]  = conv_b[tid];

    for (int idx = tid; idx < 256; idx += 128) {
        int c = idx >> 4, dd = idx & 15;
        int ch = chars[(b*SQL + s)*16 + c];
        ce[idx] = char_emb[ch*16 + dd];
    }
    int w = words[b*SQL + s];
    int row = s*BB + b;
    for (int i = tid; i < 300; i += 128)
        X[(size_t)row*LDXP + i] = __float2bfloat16(word_emb[w*300 + i]);
    __syncthreads();

    int o = tid >> 3, l = tid & 7;
    float w0 = wsh[o*3], w1 = wsh[o*3+1], w2 = wsh[o*3+2];
    float mx = -1e30f;
    for (int t = l; t < 254; t += 8) {
        float v = ce[t]*w0 + ce[t+1]*w1 + ce[t+2]*w2;
        mx = fmaxf(mx, v);
    }
    #pragma unroll
    for (int off = 4; off; off >>= 1)
        mx = fmaxf(mx, __shfl_down_sync(0xffffffffu, mx, off, 8));
    if (l == 0) {
        float v = mx + cb[o];
        if (b != 0) v = fmaxf(v, 0.f);   // reference quirk: batch row 0 skips relu
        X[(size_t)row*LDXP + 300 + o] = __float2bfloat16(v);
    }
}

// ------------------------- bf16 tensor-core GEMM ---------------------------
// Y = X @ W^T + (bih+bhh); X: [6144, d] bf16 ld=LDXP; W: [400, d] fp32; Y fp32.
// BM=128, BN=64, BK=64; 8 warps, warp tile 32x32 via mma.m16n8k16.bf16;
// double-buffered smem (one sync/chunk); 72-elem row stride = conflict-free.
#define SAW 72
#define SA_ELEMS (128*SAW)
#define SB_ELEMS (64*SAW)

__device__ __forceinline__ void mma_bf16(float* c, const uint32_t* a, const uint32_t* b) {
    asm volatile(
        "mma.sync.aligned.m16n8k16.row.col.f32.bf16.bf16.f32 "
        "{%0,%1,%2,%3}, {%4,%5,%6,%7}, {%8,%9}, {%0,%1,%2,%3};"
        : "+f"(c[0]), "+f"(c[1]), "+f"(c[2]), "+f"(c[3])
        : "r"(a[0]), "r"(a[1]), "r"(a[2]), "r"(a[3]), "r"(b[0]), "r"(b[1]));
}

__global__ __launch_bounds__(256) void gemm_wih_bf16(
    const float* __restrict__ W, const float* __restrict__ bih,
    const float* __restrict__ bhh, int d)
{
    const __nv_bfloat16* X = blockIdx.z ? g_HX : g_PX;
    float* Y               = blockIdx.z ? g_GH : g_GP;
    extern __shared__ __align__(16) unsigned char smraw[];
    __nv_bfloat16* SA = (__nv_bfloat16*)smraw;        // [2][128*72]
    __nv_bfloat16* SB = SA + 2*SA_ELEMS;              // [2][64*72]

    int tid  = threadIdx.x;
    int wid  = tid >> 5, lane = tid & 31;
    int wm   = wid >> 1, wn = wid & 1;
    int m0   = blockIdx.y * 128;
    int n0   = blockIdx.x * 64;
    int lg   = lane >> 2;      // 0..7
    int lk   = lane & 3;       // 0..3

    float acc[2][4][4];
    #pragma unroll
    for (int i = 0; i < 2; i++)
        #pragma unroll
        for (int j = 0; j < 4; j++)
            #pragma unroll
            for (int r = 0; r < 4; r++) acc[i][j][r] = 0.f;

    int nChunk = (d + 63) >> 6;

    // staging registers
    uint4 av[4];
    uint2 bv[4];

    // ---- loaders ----
    auto loadA = [&](int k0) {
        #pragma unroll
        for (int q = 0; q < 4; q++) {
            int idx = q*256 + tid;
            int row = idx >> 3, c16 = idx & 7;
            int c0  = k0 + c16*8;
            uint4 v = make_uint4(0u,0u,0u,0u);
            if (c0 < d) {
                v = *reinterpret_cast<const uint4*>(&X[(size_t)(m0+row)*LDXP + c0]);
                if (c0 + 8 > d) { v.z = 0u; v.w = 0u; }   // d % 8 == 4 always
            }
            av[q] = v;
        }
    };
    auto loadB = [&](int k0) {
        #pragma unroll
        for (int q = 0; q < 4; q++) {
            int idx = q*256 + tid;
            int row = idx >> 4, c4 = idx & 15;
            int c   = k0 + c4*4;
            float4 v = make_float4(0.f,0.f,0.f,0.f);
            if (n0 + row < 400 && c < d)
                v = *reinterpret_cast<const float4*>(&W[(size_t)(n0+row)*d + c]);
            __nv_bfloat162 lo = __float22bfloat162_rn(make_float2(v.x, v.y));
            __nv_bfloat162 hi = __float22bfloat162_rn(make_float2(v.z, v.w));
            bv[q] = make_uint2(*reinterpret_cast<uint32_t*>(&lo),
                               *reinterpret_cast<uint32_t*>(&hi));
        }
    };
    auto storeStage = [&](int st) {
        __nv_bfloat16* sa = SA + st*SA_ELEMS;
        __nv_bfloat16* sb = SB + st*SB_ELEMS;
        #pragma unroll
        for (int q = 0; q < 4; q++) {
            int idx = q*256 + tid;
            int row = idx >> 3, c16 = idx & 7;
            *reinterpret_cast<uint4*>(&sa[row*SAW + c16*8]) = av[q];
        }
        #pragma unroll
        for (int q = 0; q < 4; q++) {
            int idx = q*256 + tid;
            int row = idx >> 4, c4 = idx & 15;
            *reinterpret_cast<uint2*>(&sb[row*SAW + c4*4]) = bv[q];
        }
    };

    loadA(0); loadB(0);
    storeStage(0);
    __syncthreads();

    for (int kc = 0; kc < nChunk; kc++) {
        int cur = kc & 1;
        if (kc + 1 < nChunk) { loadA((kc+1) << 6); loadB((kc+1) << 6); }

        const __nv_bfloat16* sa = SA + cur*SA_ELEMS;
        const __nv_bfloat16* sb = SB + cur*SB_ELEMS;
        #pragma unroll
        for (int s = 0; s < 4; s++) {
            int kk = s*16 + 2*lk;
            uint32_t a[2][4], b[4][2];
            #pragma unroll
            for (int mt = 0; mt < 2; mt++) {
                int r0 = wm*32 + mt*16 + lg;
                a[mt][0] = *reinterpret_cast<const uint32_t*>(&sa[r0*SAW + kk]);
                a[mt][1] = *reinterpret_cast<const uint32_t*>(&sa[(r0+8)*SAW + kk]);
                a[mt][2] = *reinterpret_cast<const uint32_t*>(&sa[r0*SAW + kk + 8]);
                a[mt][3] = *reinterpret_cast<const uint32_t*>(&sa[(r0+8)*SAW + kk + 8]);
            }
            #pragma unroll
            for (int nt = 0; nt < 4; nt++) {
                int nr = wn*32 + nt*8 + lg;
                b[nt][0] = *reinterpret_cast<const uint32_t*>(&sb[nr*SAW + kk]);
                b[nt][1] = *reinterpret_cast<const uint32_t*>(&sb[nr*SAW + kk + 8]);
            }
            #pragma unroll
            for (int mt = 0; mt < 2; mt++)
                #pragma unroll
                for (int nt = 0; nt < 4; nt++)
                    mma_bf16(acc[mt][nt], a[mt], b[nt]);
        }

        if (kc + 1 < nChunk) storeStage(cur ^ 1);
        __syncthreads();
    }

    #pragma unroll
    for (int mt = 0; mt < 2; mt++) {
        int row0 = m0 + wm*32 + mt*16 + lg;
        #pragma unroll
        for (int nt = 0; nt < 4; nt++) {
            int col0 = n0 + wn*32 + nt*8 + 2*lk;
            if (col0 < 400) {
                float bs0 = bih[col0]   + bhh[col0];
                float bs1 = bih[col0+1] + bhh[col0+1];
                Y[(size_t)row0*400 + col0]       = acc[mt][nt][0] + bs0;
                Y[(size_t)row0*400 + col0+1]     = acc[mt][nt][1] + bs1;
                Y[(size_t)(row0+8)*400 + col0]   = acc[mt][nt][2] + bs0;
                Y[(size_t)(row0+8)*400 + col0+1] = acc[mt][nt][3] + bs1;
            }
        }
    }
}

// ------------------------- LSTM recurrence ---------------------------------
// 128 blocks (single wave); block handles (seq, b) and (seq, b+64).
// 1024 threads: 10-way split of h (w[4][10] = 40 regs/thread); gates for t+1
// prefetched during step t.
__device__ __forceinline__ float sigmf(float x) { return 1.f/(1.f+__expf(-x)); }
__device__ __forceinline__ float tanhf_fast(float x) { return 1.f - 2.f/(__expf(2.f*x)+1.f); }

__global__ __launch_bounds__(1024,1) void lstm_kernel(
    const float* __restrict__ whh, int dk, int writeX)
{
    int blk = blockIdx.x;        // 0..127
    int seq = blk >> 6;
    int bp  = blk & 63;
    const float* G = seq ? g_GH : g_GP;
    float* Hout            = seq ? g_HHs : g_PH;
    __nv_bfloat16* Xout    = seq ? g_HX  : g_PX;
    int bA = bp, bB = bp + 64;

    int tid  = threadIdx.x;
    int j    = tid % 100;
    int part = tid / 100;        // 0..10 (part 10 idle)

    __shared__ float  h_s[2][100];
    __shared__ float4 ps4[2][10][100];
    __shared__ float  gcur[2][400];

    float w[4][10];
    if (part < 10) {
        #pragma unroll
        for (int q = 0; q < 4; q++)
            #pragma unroll
            for (int ii = 0; ii < 10; ii++)
                w[q][ii] = whh[(q*100 + j)*100 + part*10 + ii];
    }

    float ga = 0.f, gb = 0.f;
    if (tid < 400) {
        ga = G[(size_t)bA*400 + tid];
        gb = G[(size_t)bB*400 + tid];
    }
    float c = 0.f;
    if (tid < 100) { h_s[0][tid] = 0.f; h_s[1][tid] = 0.f; }
    __syncthreads();

    for (int t = 0; t < 48; t++) {
        if (tid < 400) { gcur[0][tid] = ga; gcur[1][tid] = gb; }
        if (part < 10) {
            float4 aa = make_float4(0.f,0.f,0.f,0.f);
            float4 ab = make_float4(0.f,0.f,0.f,0.f);
            int base = part*10;
            #pragma unroll
            for (int ii = 0; ii < 10; ii++) {
                float ha = h_s[0][base+ii];
                float hb = h_s[1][base+ii];
                aa.x += ha*w[0][ii]; aa.y += ha*w[1][ii];
                aa.z += ha*w[2][ii]; aa.w += ha*w[3][ii];
                ab.x += hb*w[0][ii]; ab.y += hb*w[1][ii];
                ab.z += hb*w[2][ii]; ab.w += hb*w[3][ii];
            }
            ps4[0][part][j] = aa;
            ps4[1][part][j] = ab;
        }
        if (t+1 < 48 && tid < 400) {   // prefetch next step's gates
            ga = G[(size_t)((t+1)*128 + bA)*400 + tid];
            gb = G[(size_t)((t+1)*128 + bB)*400 + tid];
        }
        __syncthreads();
        if (tid < 200) {               // part == bi here (0 or 1)
            int bi = part;
            float gi = gcur[bi][j],     gf = gcur[bi][100+j];
            float gg = gcur[bi][200+j], go = gcur[bi][300+j];
            #pragma unroll
            for (int p = 0; p < 10; p++) {
                float4 v = ps4[bi][p][j];
                gi += v.x; gf += v.y; gg += v.z; go += v.w;
            }
            c = sigmf(gf)*c + sigmf(gi)*tanhf_fast(gg);
            float h = sigmf(go)*tanhf_fast(c);
            h_s[bi][j] = h;
            int b = bi ? bB : bA;
            Hout[(size_t)(t*128+b)*100 + j] = h;
            if (writeX)
                Xout[(size_t)(t*128+b)*LDXP + dk + 100 + j] = __float2bfloat16(h);
        }
        __syncthreads();
    }
}

// ------------------------- cross attention ---------------------------------
__global__ __launch_bounds__(256) void attn_kernel(int dk)
{
    extern __shared__ float smem[];
    float* hp   = smem;            // 4800
    float* hh   = smem + 4800;     // 4800
    float* attn = smem + 9600;     // 2304
    float* E    = smem + 11904;    // 2304
    float* rmax = smem + 14208;    // 48
    float* rsum = rmax + 48;
    float* cmax = rsum + 48;
    float* csum = cmax + 48;

    int b = blockIdx.x;
    int tid = threadIdx.x;

    for (int idx = tid; idx < 4800; idx += 256) {
        int s = idx / 100, h2 = idx % 100;
        hp[idx] = g_PH [(size_t)(s*128+b)*100 + h2];
        hh[idx] = g_HHs[(size_t)(s*128+b)*100 + h2];
    }
    __syncthreads();

    for (int idx = tid; idx < 2304; idx += 256) {
        int p = idx / 48, q = idx % 48;
        const float* hpp = hp + p*100;
        const float* hhq = hh + q*100;
        float a = 0.f;
        #pragma unroll 4
        for (int i = 0; i < 100; i++) a += hpp[i]*hhq[i];
        attn[idx] = a;
    }
    __syncthreads();

    if (tid < 48) {
        float m = -1e30f;
        for (int q = 0; q < 48; q++) m = fmaxf(m, attn[tid*48+q]);
        float s2 = 0.f;
        for (int q = 0; q < 48; q++) s2 += expf(attn[tid*48+q]-m);
        rmax[tid] = m; rsum[tid] = s2;
    } else if (tid >= 128 && tid < 176) {
        int q = tid - 128;
        float m = -1e30f;
        for (int p = 0; p < 48; p++) m = fmaxf(m, attn[p*48+q]);
        float s2 = 0.f;
        for (int p = 0; p < 48; p++) s2 += expf(attn[p*48+q]-m);
        cmax[q] = m; csum[q] = s2;
    }
    __syncthreads();

    for (int idx = tid; idx < 2304; idx += 256) {
        int p = idx / 48;
        E[idx] = expf(attn[idx]-rmax[p]) / rsum[p];
    }
    __syncthreads();
    for (int idx = tid; idx < 4800; idx += 256) {
        int p = idx / 100, h2 = idx % 100;
        float a = 0.f;
        #pragma unroll 4
        for (int q = 0; q < 48; q++) a += E[p*48+q]*hh[q*100+h2];
        g_PX[(size_t)(p*128+b)*LDXP + dk + h2] = __float2bfloat16(a);
    }
    __syncthreads();

    for (int idx = tid; idx < 2304; idx += 256) {
        int q = idx % 48;
        E[idx] = expf(attn[idx]-cmax[q]) / csum[q];
    }
    __syncthreads();
    for (int idx = tid; idx < 4800; idx += 256) {
        int q = idx / 100, h2 = idx % 100;
        float a = 0.f;
        #pragma unroll 4
        for (int p = 0; p < 48; p++) a += E[p*48+q]*hp[p*100+h2];
        g_HX[(size_t)(q*128+b)*LDXP + dk + h2] = __float2bfloat16(a);
    }
}

// ------------------------- pooling + FC head -------------------------------
__global__ __launch_bounds__(256) void head_kernel(
    const float* __restrict__ fcl_w, const float* __restrict__ fcl_b,
    const float* __restrict__ last_w, const float* __restrict__ last_b,
    float* __restrict__ out)
{
    __shared__ float feats[500];
    __shared__ float o1[800];
    __shared__ float red[256];
    int b = blockIdx.x, tid = threadIdx.x;

    if (tid < 100) {
        float hq = -1e30f, hs = -1e30f;
        for (int s = 0; s < 48; s++) {
            hq = fmaxf(hq, g_PH [(size_t)(s*128+b)*100 + tid]);
            hs = fmaxf(hs, g_HHs[(size_t)(s*128+b)*100 + tid]);
        }
        feats[tid]       = hq;
        feats[100 + tid] = hs;
        feats[200 + tid] = hs - hq;
        feats[300 + tid] = hq * hs;
        feats[400 + tid] = fabsf(hq - hs);
    }
    __syncthreads();

    for (int o = tid; o < 800; o += 256) {
        float a = fcl_b[o];
        const float* wr = fcl_w + (size_t)o*500;
        #pragma unroll 4
        for (int k = 0; k < 500; k++) a += feats[k]*wr[k];
        o1[o] = fmaxf(a, 0.f);
    }
    __syncthreads();

    for (int cc = 0; cc < 2; cc++) {
        float pa = 0.f;
        for (int o = tid; o < 800; o += 256) pa += o1[o]*last_w[cc*800+o];
        red[tid] = pa;
        __syncthreads();
        for (int off = 128; off; off >>= 1) {
            if (tid < off) red[tid] += red[tid+off];
            __syncthreads();
        }
        if (tid == 0) {
            float v = red[0] + last_b[cc];
            out[b*2+cc] = 1.f/(1.f+expf(-v));
        }
        __syncthreads();
    }
}

// ------------------------- launch ------------------------------------------
extern "C" void kernel_launch(void* const* d_in, const int* in_sizes, int n_in,
                              void* d_out, int out_size)
{
    const int*   q_words  = (const int*)d_in[0];
    const int*   q_chars  = (const int*)d_in[1];
    const int*   s_words  = (const int*)d_in[2];
    const int*   s_chars  = (const int*)d_in[3];
    const float* word_emb = (const float*)d_in[4];
    const float* char_emb = (const float*)d_in[5];
    const float* conv_w   = (const float*)d_in[6];
    const float* conv_b   = (const float*)d_in[7];
    const float* fcl_w    = (const float*)d_in[28];
    const float* fcl_b    = (const float*)d_in[29];
    const float* last_w   = (const float*)d_in[30];
    const float* last_b   = (const float*)d_in[31];
    float* out = (float*)d_out;

    const int gemm_smem = 2*(SA_ELEMS + SB_ELEMS)*2;   // 55296 bytes
    cudaFuncSetAttribute(gemm_wih_bf16, cudaFuncAttributeMaxDynamicSharedMemorySize, gemm_smem);
    cudaFuncSetAttribute(attn_kernel, cudaFuncAttributeMaxDynamicSharedMemorySize, 57600);

    embed_kernel<<<6144,128>>>(q_words, q_chars, word_emb, char_emb, conv_w, conv_b, 0);
    embed_kernel<<<6144,128>>>(s_words, s_chars, word_emb, char_emb, conv_w, conv_b, 1);

    const int dims[5] = {316, 516, 716, 916, 1116};
    for (int k = 0; k < 5; k++) {
        const float* wih = (const float*)d_in[8+4*k];
        const float* whh = (const float*)d_in[9+4*k];
        const float* bih = (const float*)d_in[10+4*k];
        const float* bhh = (const float*)d_in[11+4*k];
        dim3 gg(7, 48, 2);
        gemm_wih_bf16<<<gg, 256, gemm_smem>>>(wih, bih, bhh, dims[k]);
        lstm_kernel<<<128, 1024>>>(whh, dims[k], (k < 4) ? 1 : 0);
        if (k < 4) attn_kernel<<<128, 256, 57600>>>(dims[k]);
    }
    head_kernel<<<128, 256>>>(fcl_w, fcl_b, last_w, last_b, out);
}

// round 6
// speedup vs baseline: 2.6873x; 2.0760x over previous
#include <cuda_runtime.h>
#include <cuda_bf16.h>
#include <math.h>
#include <stdint.h>

#define SQL 48
#define BB  128
#define HDIM 100
#define LDXP 1120   // padded feature width (bf16 rows, 16B-aligned)

typedef unsigned long long ull;

// ------------------------- scratch (device globals; no allocs) -------------
__device__ __nv_bfloat16 g_PX[SQL*BB*LDXP];  // query features (bf16, gemm input)
__device__ __nv_bfloat16 g_HX[SQL*BB*LDXP];  // support features
__device__ __nv_bfloat16 g_W16[400*LDXP];    // current layer wih in bf16 (zero-padded)
__device__ float g_GP[SQL*BB*400];           // x@wih^T + biases (query)
__device__ float g_GH[SQL*BB*400];           // (support)
__device__ float g_PH[SQL*BB*HDIM];          // hidden states (query, fp32)
__device__ float g_HHs[SQL*BB*HDIM];         // (support)

// ------------------------- f32x2 helpers -----------------------------------
__device__ __forceinline__ void fma2(ull &d, ull a, ull b) {
    asm("fma.rn.f32x2 %0, %1, %2, %0;" : "+l"(d) : "l"(a), "l"(b));
}
__device__ __forceinline__ ull bcast2(float x) {
    ull r; asm("mov.b64 %0, {%1, %1};" : "=l"(r) : "f"(x)); return r;
}
__device__ __forceinline__ float hsum2(ull a) {
    float2 v = *reinterpret_cast<float2*>(&a); return v.x + v.y;
}

// ------------------------- embedding + char conv ---------------------------
__global__ __launch_bounds__(128) void embed_kernel(
    const int* __restrict__ words, const int* __restrict__ chars,
    const float* __restrict__ word_emb, const float* __restrict__ char_emb,
    const float* __restrict__ conv_w, const float* __restrict__ conv_b,
    int which)
{
    __nv_bfloat16* X = which ? g_HX : g_PX;
    int m = blockIdx.x;       // 0..6143
    int b = m / SQL;
    int s = m % SQL;
    int tid = threadIdx.x;

    __shared__ float ce[256];
    __shared__ float wsh[48];
    __shared__ float cb[16];
    if (tid < 48) wsh[tid] = conv_w[tid];
    if (tid < 16) cb[tid]  = conv_b[tid];

    for (int idx = tid; idx < 256; idx += 128) {
        int c = idx >> 4, dd = idx & 15;
        int ch = chars[(b*SQL + s)*16 + c];
        ce[idx] = char_emb[ch*16 + dd];
    }
    int w = words[b*SQL + s];
    int row = s*BB + b;
    if (tid < 75) {   // 300 floats = 75 float4
        float4 v = *reinterpret_cast<const float4*>(&word_emb[(size_t)w*300 + tid*4]);
        __nv_bfloat162 lo = __float22bfloat162_rn(make_float2(v.x, v.y));
        __nv_bfloat162 hi = __float22bfloat162_rn(make_float2(v.z, v.w));
        *reinterpret_cast<__nv_bfloat162*>(&X[(size_t)row*LDXP + tid*4])     = lo;
        *reinterpret_cast<__nv_bfloat162*>(&X[(size_t)row*LDXP + tid*4 + 2]) = hi;
    }
    __syncthreads();

    int o = tid >> 3, l = tid & 7;
    float w0 = wsh[o*3], w1 = wsh[o*3+1], w2 = wsh[o*3+2];
    float mx = -1e30f;
    for (int t = l; t < 254; t += 8) {
        float v = ce[t]*w0 + ce[t+1]*w1 + ce[t+2]*w2;
        mx = fmaxf(mx, v);
    }
    #pragma unroll
    for (int off = 4; off; off >>= 1)
        mx = fmaxf(mx, __shfl_down_sync(0xffffffffu, mx, off, 8));
    if (l == 0) {
        float v = mx + cb[o];
        if (b != 0) v = fmaxf(v, 0.f);   // reference quirk: batch row 0 skips relu
        X[(size_t)row*LDXP + 300 + o] = __float2bfloat16(v);
    }
}

// ------------------------- wih fp32 -> bf16 convert ------------------------
__global__ __launch_bounds__(128) void convert_w(const float* __restrict__ W, int d)
{
    int row = blockIdx.x;       // 0..399
    int tid = threadIdx.x;
    for (int c = tid; c < LDXP; c += 128) {
        float v = (c < d) ? W[(size_t)row*d + c] : 0.f;
        g_W16[(size_t)row*LDXP + c] = __float2bfloat16(v);
    }
}

// ------------------------- bf16 tensor-core GEMM ---------------------------
// Y = X @ W^T + (bih+bhh); X: [6144, d] bf16 ld=LDXP; W16: [400, 1120] bf16.
// BM=128, BN=64, BK=64; 8 warps, warp tile 32x32 via mma.m16n8k16.bf16;
// double-buffered smem; ldmatrix fragment loads; 72-elem (144B) row stride.
#define SAW 72
#define SA_ELEMS (128*SAW)
#define SB_ELEMS (64*SAW)

__device__ __forceinline__ void mma_bf16(float* c, const uint32_t* a, const uint32_t* b) {
    asm volatile(
        "mma.sync.aligned.m16n8k16.row.col.f32.bf16.bf16.f32 "
        "{%0,%1,%2,%3}, {%4,%5,%6,%7}, {%8,%9}, {%0,%1,%2,%3};"
        : "+f"(c[0]), "+f"(c[1]), "+f"(c[2]), "+f"(c[3])
        : "r"(a[0]), "r"(a[1]), "r"(a[2]), "r"(a[3]), "r"(b[0]), "r"(b[1]));
}
__device__ __forceinline__ void ldsm_x4(uint32_t& r0, uint32_t& r1, uint32_t& r2, uint32_t& r3,
                                        uint32_t addr) {
    asm volatile("ldmatrix.sync.aligned.m8n8.x4.shared.b16 {%0,%1,%2,%3}, [%4];"
        : "=r"(r0), "=r"(r1), "=r"(r2), "=r"(r3) : "r"(addr));
}

__global__ __launch_bounds__(256) void gemm_wih_bf16(
    const float* __restrict__ bih, const float* __restrict__ bhh, int d)
{
    const __nv_bfloat16* X = blockIdx.z ? g_HX : g_PX;
    float* Y               = blockIdx.z ? g_GH : g_GP;
    extern __shared__ __align__(16) unsigned char smraw[];
    __nv_bfloat16* SA = (__nv_bfloat16*)smraw;        // [2][128*72]
    __nv_bfloat16* SB = SA + 2*SA_ELEMS;              // [2][64*72]

    int tid  = threadIdx.x;
    int wid  = tid >> 5, lane = tid & 31;
    int wm   = wid >> 1, wn = wid & 1;
    int m0   = blockIdx.y * 128;
    int n0   = blockIdx.x * 64;
    int lg   = lane >> 2;      // 0..7
    int lk   = lane & 3;       // 0..3

    // ldmatrix per-lane address components (element offsets)
    int a_roff = (wm*32 + (lane & 15)) * SAW + ((lane & 16) ? 8 : 0);
    int b_roff = (wn*32 + (lane & 7) + ((lane & 16) ? 8 : 0)) * SAW + ((lane & 8) ? 8 : 0);

    float acc[2][4][4];
    #pragma unroll
    for (int i = 0; i < 2; i++)
        #pragma unroll
        for (int j = 0; j < 4; j++)
            #pragma unroll
            for (int r = 0; r < 4; r++) acc[i][j][r] = 0.f;

    int nChunk = (d + 63) >> 6;

    uint4 av[4];
    uint4 bv[2];

    auto loadA = [&](int k0) {
        #pragma unroll
        for (int q = 0; q < 4; q++) {
            int idx = q*256 + tid;
            int row = idx >> 3, c16 = idx & 7;
            int c0  = k0 + c16*8;
            uint4 v = make_uint4(0u,0u,0u,0u);
            if (c0 < d) {
                v = *reinterpret_cast<const uint4*>(&X[(size_t)(m0+row)*LDXP + c0]);
                if (c0 + 8 > d) { v.z = 0u; v.w = 0u; }   // d % 8 == 4 always
            }
            av[q] = v;
        }
    };
    auto loadB = [&](int k0) {
        #pragma unroll
        for (int q = 0; q < 2; q++) {
            int idx = q*256 + tid;
            int row = idx >> 3, c16 = idx & 7;
            int c0  = k0 + c16*8;
            uint4 v = make_uint4(0u,0u,0u,0u);
            if (n0 + row < 400 && c0 < LDXP)   // W16 zero-padded to LDXP
                v = *reinterpret_cast<const uint4*>(&g_W16[(size_t)(n0+row)*LDXP + c0]);
            bv[q] = v;
        }
    };
    auto storeStage = [&](int st) {
        __nv_bfloat16* sa = SA + st*SA_ELEMS;
        __nv_bfloat16* sb = SB + st*SB_ELEMS;
        #pragma unroll
        for (int q = 0; q < 4; q++) {
            int idx = q*256 + tid;
            int row = idx >> 3, c16 = idx & 7;
            *reinterpret_cast<uint4*>(&sa[row*SAW + c16*8]) = av[q];
        }
        #pragma unroll
        for (int q = 0; q < 2; q++) {
            int idx = q*256 + tid;
            int row = idx >> 3, c16 = idx & 7;
            *reinterpret_cast<uint4*>(&sb[row*SAW + c16*8]) = bv[q];
        }
    };

    loadA(0); loadB(0);
    storeStage(0);
    __syncthreads();

    for (int kc = 0; kc < nChunk; kc++) {
        int cur = kc & 1;
        if (kc + 1 < nChunk) { loadA((kc+1) << 6); loadB((kc+1) << 6); }

        uint32_t sa_u = (uint32_t)__cvta_generic_to_shared(SA + cur*SA_ELEMS);
        uint32_t sb_u = (uint32_t)__cvta_generic_to_shared(SB + cur*SB_ELEMS);
        #pragma unroll
        for (int s = 0; s < 4; s++) {
            uint32_t a[2][4], b[4][2];
            #pragma unroll
            for (int mt = 0; mt < 2; mt++)
                ldsm_x4(a[mt][0], a[mt][1], a[mt][2], a[mt][3],
                        sa_u + 2*(a_roff + mt*16*SAW + s*16));
            #pragma unroll
            for (int ntp = 0; ntp < 2; ntp++) {
                uint32_t r0, r1, r2, r3;
                ldsm_x4(r0, r1, r2, r3, sb_u + 2*(b_roff + ntp*16*SAW + s*16));
                b[2*ntp][0] = r0; b[2*ntp][1] = r1;
                b[2*ntp+1][0] = r2; b[2*ntp+1][1] = r3;
            }
            #pragma unroll
            for (int mt = 0; mt < 2; mt++)
                #pragma unroll
                for (int nt = 0; nt < 4; nt++)
                    mma_bf16(acc[mt][nt], a[mt], b[nt]);
        }

        if (kc + 1 < nChunk) storeStage(cur ^ 1);
        __syncthreads();
    }

    #pragma unroll
    for (int mt = 0; mt < 2; mt++) {
        int row0 = m0 + wm*32 + mt*16 + lg;
        #pragma unroll
        for (int nt = 0; nt < 4; nt++) {
            int col0 = n0 + wn*32 + nt*8 + 2*lk;
            if (col0 < 400) {
                float bs0 = bih[col0]   + bhh[col0];
                float bs1 = bih[col0+1] + bhh[col0+1];
                Y[(size_t)row0*400 + col0]       = acc[mt][nt][0] + bs0;
                Y[(size_t)row0*400 + col0+1]     = acc[mt][nt][1] + bs1;
                Y[(size_t)(row0+8)*400 + col0]   = acc[mt][nt][2] + bs0;
                Y[(size_t)(row0+8)*400 + col0+1] = acc[mt][nt][3] + bs1;
            }
        }
    }
}

// ------------------------- LSTM recurrence ---------------------------------
// 512 threads, 128 blocks (single wave); block handles (seq, bp) and (seq, bp+64).
// 5-way h split; whh packed as f32x2 pairs in registers (fma.rn.f32x2 = 2 MAC/issue).
// Combiner threads (tid<200) keep gate vectors for t+1 in registers.
__device__ __forceinline__ float sigmf(float x) { return 1.f/(1.f+__expf(-x)); }
__device__ __forceinline__ float tanhf_fast(float x) { return 1.f - 2.f/(__expf(2.f*x)+1.f); }

__global__ __launch_bounds__(512,1) void lstm_kernel(
    const float* __restrict__ whh, int dk, int writeX)
{
    int blk = blockIdx.x;        // 0..127
    int seq = blk >> 6;
    int bp  = blk & 63;
    const float* G = seq ? g_GH : g_GP;
    float* Hout         = seq ? g_HHs : g_PH;
    __nv_bfloat16* Xout = seq ? g_HX  : g_PX;

    int tid  = threadIdx.x;
    int j    = tid % 100;
    int part = tid / 100;        // 0..4 producers; 5 idle tail

    __shared__ __align__(16) float  h_s[2][100];
    __shared__ __align__(16) float4 ps4[2][5][100];

    ull w2[4][10];
    if (part < 5) {
        #pragma unroll
        for (int q = 0; q < 4; q++)
            #pragma unroll
            for (int m = 0; m < 10; m++)
                w2[q][m] = *reinterpret_cast<const ull*>(
                    &whh[(size_t)(q*100 + j)*100 + part*20 + 2*m]);
    }

    // combiner state (tid<200): bi = part (0/1)
    int bi = part;
    int b  = bi ? bp + 64 : bp;
    float c = 0.f;
    float gr0 = 0.f, gr1 = 0.f, gr2 = 0.f, gr3 = 0.f;
    if (tid < 200) {
        const float* G0 = G + (size_t)b*400;
        gr0 = G0[j]; gr1 = G0[100+j]; gr2 = G0[200+j]; gr3 = G0[300+j];
    }
    if (tid < 100) { h_s[0][tid] = 0.f; h_s[1][tid] = 0.f; }
    __syncthreads();

    for (int t = 0; t < 48; t++) {
        if (part < 5) {
            #pragma unroll
            for (int b2 = 0; b2 < 2; b2++) {
                const ull* hp = reinterpret_cast<const ull*>(&h_s[b2][part*20]);
                ull a0 = 0, a1 = 0, a2 = 0, a3 = 0;
                #pragma unroll
                for (int m = 0; m < 10; m++) {
                    ull h2 = hp[m];
                    fma2(a0, h2, w2[0][m]);
                    fma2(a1, h2, w2[1][m]);
                    fma2(a2, h2, w2[2][m]);
                    fma2(a3, h2, w2[3][m]);
                }
                ps4[b2][part][j] = make_float4(hsum2(a0), hsum2(a1), hsum2(a2), hsum2(a3));
            }
        }
        __syncthreads();
        if (tid < 200) {
            float gi = gr0, gf = gr1, gg = gr2, go = gr3;
            #pragma unroll
            for (int p = 0; p < 5; p++) {
                float4 v = ps4[bi][p][j];
                gi += v.x; gf += v.y; gg += v.z; go += v.w;
            }
            if (t + 1 < 48) {   // prefetch next step's gates (registers)
                const float* Gn = G + (size_t)((t+1)*128 + b)*400;
                gr0 = Gn[j]; gr1 = Gn[100+j]; gr2 = Gn[200+j]; gr3 = Gn[300+j];
            }
            c = sigmf(gf)*c + sigmf(gi)*tanhf_fast(gg);
            float h = sigmf(go)*tanhf_fast(c);
            h_s[bi][j] = h;
            Hout[(size_t)(t*128+b)*100 + j] = h;
            if (writeX)
                Xout[(size_t)(t*128+b)*LDXP + dk + 100 + j] = __float2bfloat16(h);
        }
        __syncthreads();
    }
}

// ------------------------- cross attention ---------------------------------
__global__ __launch_bounds__(256) void attn_kernel(int dk)
{
    extern __shared__ __align__(16) float smem[];
    float* hp   = smem;            // 4800
    float* hh   = smem + 4800;     // 4800
    float* attn = smem + 9600;     // 2304
    float* E    = smem + 11904;    // 2304
    float* rmax = smem + 14208;    // 48
    float* rsum = rmax + 48;
    float* cmax = rsum + 48;
    float* csum = cmax + 48;

    int b = blockIdx.x;
    int tid = threadIdx.x;

    for (int idx = tid; idx < 2400; idx += 256) {
        int s = idx / 50, h2 = (idx % 50)*2;
        *reinterpret_cast<float2*>(&hp[s*100+h2]) =
            *reinterpret_cast<const float2*>(&g_PH [(size_t)(s*128+b)*100 + h2]);
        *reinterpret_cast<float2*>(&hh[s*100+h2]) =
            *reinterpret_cast<const float2*>(&g_HHs[(size_t)(s*128+b)*100 + h2]);
    }
    __syncthreads();

    for (int idx = tid; idx < 2304; idx += 256) {
        int p = idx / 48, q = idx % 48;
        const ull* ap = reinterpret_cast<const ull*>(hp + p*100);
        const ull* bq = reinterpret_cast<const ull*>(hh + q*100);
        ull acc = 0;
        #pragma unroll 5
        for (int i = 0; i < 50; i++) fma2(acc, ap[i], bq[i]);
        attn[idx] = hsum2(acc);
    }
    __syncthreads();

    if (tid < 48) {
        float m = -1e30f;
        for (int q = 0; q < 48; q++) m = fmaxf(m, attn[tid*48+q]);
        float s2 = 0.f;
        for (int q = 0; q < 48; q++) s2 += expf(attn[tid*48+q]-m);
        rmax[tid] = m; rsum[tid] = s2;
    } else if (tid >= 128 && tid < 176) {
        int q = tid - 128;
        float m = -1e30f;
        for (int p = 0; p < 48; p++) m = fmaxf(m, attn[p*48+q]);
        float s2 = 0.f;
        for (int p = 0; p < 48; p++) s2 += expf(attn[p*48+q]-m);
        cmax[q] = m; csum[q] = s2;
    }
    __syncthreads();

    for (int idx = tid; idx < 2304; idx += 256) {
        int p = idx / 48;
        E[idx] = expf(attn[idx]-rmax[p]) / rsum[p];
    }
    __syncthreads();
    for (int idx = tid; idx < 2400; idx += 256) {   // a_p: float2 outputs
        int p = idx / 50, h2p = idx % 50;
        const ull* hh2 = reinterpret_cast<const ull*>(hh) + h2p;
        ull acc = 0;
        #pragma unroll 4
        for (int q = 0; q < 48; q++) fma2(acc, bcast2(E[p*48+q]), hh2[q*50]);
        float2 r = *reinterpret_cast<float2*>(&acc);
        *reinterpret_cast<__nv_bfloat162*>(&g_PX[(size_t)(p*128+b)*LDXP + dk + 2*h2p]) =
            __float22bfloat162_rn(r);
    }
    __syncthreads();

    for (int idx = tid; idx < 2304; idx += 256) {
        int q = idx % 48;
        E[idx] = expf(attn[idx]-cmax[q]) / csum[q];
    }
    __syncthreads();
    for (int idx = tid; idx < 2400; idx += 256) {   // a_h: float2 outputs
        int q = idx / 50, h2p = idx % 50;
        const ull* hp2 = reinterpret_cast<const ull*>(hp) + h2p;
        ull acc = 0;
        #pragma unroll 4
        for (int p = 0; p < 48; p++) fma2(acc, bcast2(E[p*48+q]), hp2[p*50]);
        float2 r = *reinterpret_cast<float2*>(&acc);
        *reinterpret_cast<__nv_bfloat162*>(&g_HX[(size_t)(q*128+b)*LDXP + dk + 2*h2p]) =
            __float22bfloat162_rn(r);
    }
}

// ------------------------- pooling + FC head -------------------------------
__global__ __launch_bounds__(256) void head_kernel(
    const float* __restrict__ fcl_w, const float* __restrict__ fcl_b,
    const float* __restrict__ last_w, const float* __restrict__ last_b,
    float* __restrict__ out)
{
    __shared__ __align__(16) float feats[500];
    __shared__ float o1[800];
    __shared__ float red[256];
    int b = blockIdx.x, tid = threadIdx.x;

    if (tid < 100) {
        float hq = -1e30f, hs = -1e30f;
        for (int s = 0; s < 48; s++) {
            hq = fmaxf(hq, g_PH [(size_t)(s*128+b)*100 + tid]);
            hs = fmaxf(hs, g_HHs[(size_t)(s*128+b)*100 + tid]);
        }
        feats[tid]       = hq;
        feats[100 + tid] = hs;
        feats[200 + tid] = hs - hq;
        feats[300 + tid] = hq * hs;
        feats[400 + tid] = fabsf(hq - hs);
    }
    __syncthreads();

    for (int o = tid; o < 800; o += 256) {
        const ull* f2 = reinterpret_cast<const ull*>(feats);
        const ull* w2 = reinterpret_cast<const ull*>(fcl_w + (size_t)o*500);
        ull acc = 0;
        #pragma unroll 5
        for (int k = 0; k < 250; k++) fma2(acc, f2[k], w2[k]);
        o1[o] = fmaxf(hsum2(acc) + fcl_b[o], 0.f);
    }
    __syncthreads();

    for (int cc = 0; cc < 2; cc++) {
        float pa = 0.f;
        for (int o = tid; o < 800; o += 256) pa += o1[o]*last_w[cc*800+o];
        red[tid] = pa;
        __syncthreads();
        for (int off = 128; off; off >>= 1) {
            if (tid < off) red[tid] += red[tid+off];
            __syncthreads();
        }
        if (tid == 0) {
            float v = red[0] + last_b[cc];
            out[b*2+cc] = 1.f/(1.f+expf(-v));
        }
        __syncthreads();
    }
}

// ------------------------- launch ------------------------------------------
extern "C" void kernel_launch(void* const* d_in, const int* in_sizes, int n_in,
                              void* d_out, int out_size)
{
    const int*   q_words  = (const int*)d_in[0];
    const int*   q_chars  = (const int*)d_in[1];
    const int*   s_words  = (const int*)d_in[2];
    const int*   s_chars  = (const int*)d_in[3];
    const float* word_emb = (const float*)d_in[4];
    const float* char_emb = (const float*)d_in[5];
    const float* conv_w   = (const float*)d_in[6];
    const float* conv_b   = (const float*)d_in[7];
    const float* fcl_w    = (const float*)d_in[28];
    const float* fcl_b    = (const float*)d_in[29];
    const float* last_w   = (const float*)d_in[30];
    const float* last_b   = (const float*)d_in[31];
    float* out = (float*)d_out;

    const int gemm_smem = 2*(SA_ELEMS + SB_ELEMS)*2;   // 55296 bytes
    cudaFuncSetAttribute(gemm_wih_bf16, cudaFuncAttributeMaxDynamicSharedMemorySize, gemm_smem);
    cudaFuncSetAttribute(attn_kernel, cudaFuncAttributeMaxDynamicSharedMemorySize, 57600);

    embed_kernel<<<6144,128>>>(q_words, q_chars, word_emb, char_emb, conv_w, conv_b, 0);
    embed_kernel<<<6144,128>>>(s_words, s_chars, word_emb, char_emb, conv_w, conv_b, 1);

    const int dims[5] = {316, 516, 716, 916, 1116};
    for (int k = 0; k < 5; k++) {
        const float* wih = (const float*)d_in[8+4*k];
        const float* whh = (const float*)d_in[9+4*k];
        const float* bih = (const float*)d_in[10+4*k];
        const float* bhh = (const float*)d_in[11+4*k];
        convert_w<<<400,128>>>(wih, dims[k]);
        dim3 gg(7, 48, 2);
        gemm_wih_bf16<<<gg, 256, gemm_smem>>>(bih, bhh, dims[k]);
        lstm_kernel<<<128, 512>>>(whh, dims[k], (k < 4) ? 1 : 0);
        if (k < 4) attn_kernel<<<128, 256, 57600>>>(dims[k]);
    }
    head_kernel<<<128, 256>>>(fcl_w, fcl_b, last_w, last_b, out);
}

// round 7
// speedup vs baseline: 2.8800x; 1.0717x over previous
#include <cuda_runtime.h>
#include <cuda_bf16.h>
#include <math.h>
#include <stdint.h>

#define SQL 48
#define BB  128
#define HDIM 100
#define LDXP 1120   // padded feature width (bf16 rows, 16B-aligned)

typedef unsigned long long ull;

// ------------------------- scratch (device globals; no allocs) -------------
__device__ __nv_bfloat16 g_PX[SQL*BB*LDXP];    // query features (bf16)
__device__ __nv_bfloat16 g_HX[SQL*BB*LDXP];    // support features
__device__ __nv_bfloat16 g_W16[5*400*LDXP];    // all layers' wih in bf16 (zero-padded)
__device__ float g_GP[SQL*BB*400];             // x@wih^T + biases (query)
__device__ float g_GH[SQL*BB*400];             // (support)
__device__ float g_PH[SQL*BB*HDIM];            // hidden states (query, fp32)
__device__ float g_HHs[SQL*BB*HDIM];           // (support)

__constant__ int c_dims[5] = {316, 516, 716, 916, 1116};

// ------------------------- f32x2 helpers -----------------------------------
__device__ __forceinline__ void fma2(ull &d, ull a, ull b) {
    asm("fma.rn.f32x2 %0, %1, %2, %0;" : "+l"(d) : "l"(a), "l"(b));
}
__device__ __forceinline__ ull bcast2(float x) {
    ull r; asm("mov.b64 %0, {%1, %1};" : "=l"(r) : "f"(x)); return r;
}
__device__ __forceinline__ float hsum2(ull a) {
    float2 v = *reinterpret_cast<float2*>(&a); return v.x + v.y;
}

// ------------------------- embedding + char conv (both streams) ------------
__global__ __launch_bounds__(128) void embed_kernel(
    const int* __restrict__ q_words, const int* __restrict__ q_chars,
    const int* __restrict__ s_words, const int* __restrict__ s_chars,
    const float* __restrict__ word_emb, const float* __restrict__ char_emb,
    const float* __restrict__ conv_w, const float* __restrict__ conv_b)
{
    int which = blockIdx.y;
    const int* words = which ? s_words : q_words;
    const int* chars = which ? s_chars : q_chars;
    __nv_bfloat16* X = which ? g_HX : g_PX;
    int m = blockIdx.x;       // 0..6143
    int b = m / SQL;
    int s = m % SQL;
    int tid = threadIdx.x;

    __shared__ float ce[256];
    __shared__ float wsh[48];
    __shared__ float cb[16];
    if (tid < 48) wsh[tid] = conv_w[tid];
    if (tid < 16) cb[tid]  = conv_b[tid];

    for (int idx = tid; idx < 256; idx += 128) {
        int c = idx >> 4, dd = idx & 15;
        int ch = chars[(b*SQL + s)*16 + c];
        ce[idx] = char_emb[ch*16 + dd];
    }
    int w = words[b*SQL + s];
    int row = s*BB + b;
    if (tid < 75) {   // 300 floats = 75 float4
        float4 v = *reinterpret_cast<const float4*>(&word_emb[(size_t)w*300 + tid*4]);
        __nv_bfloat162 lo = __float22bfloat162_rn(make_float2(v.x, v.y));
        __nv_bfloat162 hi = __float22bfloat162_rn(make_float2(v.z, v.w));
        *reinterpret_cast<__nv_bfloat162*>(&X[(size_t)row*LDXP + tid*4])     = lo;
        *reinterpret_cast<__nv_bfloat162*>(&X[(size_t)row*LDXP + tid*4 + 2]) = hi;
    }
    __syncthreads();

    int o = tid >> 3, l = tid & 7;
    float w0 = wsh[o*3], w1 = wsh[o*3+1], w2 = wsh[o*3+2];
    float mx = -1e30f;
    for (int t = l; t < 254; t += 8) {
        float v = ce[t]*w0 + ce[t+1]*w1 + ce[t+2]*w2;
        mx = fmaxf(mx, v);
    }
    #pragma unroll
    for (int off = 4; off; off >>= 1)
        mx = fmaxf(mx, __shfl_down_sync(0xffffffffu, mx, off, 8));
    if (l == 0) {
        float v = mx + cb[o];
        if (b != 0) v = fmaxf(v, 0.f);   // reference quirk: batch row 0 skips relu
        X[(size_t)row*LDXP + 300 + o] = __float2bfloat16(v);
    }
}

// ------------------------- all wih fp32 -> bf16 (one launch, off loop) -----
__global__ __launch_bounds__(128) void convert_w_all(
    const float* __restrict__ W0, const float* __restrict__ W1,
    const float* __restrict__ W2, const float* __restrict__ W3,
    const float* __restrict__ W4)
{
    int layer = blockIdx.x / 400;
    int row   = blockIdx.x % 400;
    const float* Wp[5] = {W0, W1, W2, W3, W4};
    const float* W = Wp[layer];
    int d = c_dims[layer];
    __nv_bfloat16* dst = g_W16 + ((size_t)layer*400 + row)*LDXP;
    int tid = threadIdx.x;
    for (int c = tid; c < LDXP; c += 128) {
        float v = (c < d) ? W[(size_t)row*d + c] : 0.f;
        dst[c] = __float2bfloat16(v);
    }
}

// ------------------------- bf16 tensor-core GEMM (cp.async) ----------------
// Y = X @ W^T + (bih+bhh); X: [6144, d] bf16 ld=LDXP; W16: [400, 1120] bf16.
// BM=128, BN=64, BK=64; 8 warps, 32x32 warp tiles via mma.m16n8k16.bf16;
// cp.async double-buffered smem; ldmatrix fragment loads; 72-elem row stride.
#define SAW 72
#define SA_ELEMS (128*SAW)
#define SB_ELEMS (64*SAW)

__device__ __forceinline__ void mma_bf16(float* c, const uint32_t* a, const uint32_t* b) {
    asm volatile(
        "mma.sync.aligned.m16n8k16.row.col.f32.bf16.bf16.f32 "
        "{%0,%1,%2,%3}, {%4,%5,%6,%7}, {%8,%9}, {%0,%1,%2,%3};"
        : "+f"(c[0]), "+f"(c[1]), "+f"(c[2]), "+f"(c[3])
        : "r"(a[0]), "r"(a[1]), "r"(a[2]), "r"(a[3]), "r"(b[0]), "r"(b[1]));
}
__device__ __forceinline__ void ldsm_x4(uint32_t& r0, uint32_t& r1, uint32_t& r2, uint32_t& r3,
                                        uint32_t addr) {
    asm volatile("ldmatrix.sync.aligned.m8n8.x4.shared.b16 {%0,%1,%2,%3}, [%4];"
        : "=r"(r0), "=r"(r1), "=r"(r2), "=r"(r3) : "r"(addr));
}
__device__ __forceinline__ void cp_async16(uint32_t smem, const void* g, int src_bytes) {
    asm volatile("cp.async.cg.shared.global [%0], [%1], 16, %2;"
        :: "r"(smem), "l"(g), "r"(src_bytes));
}
__device__ __forceinline__ void cp_commit() {
    asm volatile("cp.async.commit_group;");
}
template<int N>
__device__ __forceinline__ void cp_wait() {
    asm volatile("cp.async.wait_group %0;" :: "n"(N));
}

__global__ __launch_bounds__(256) void gemm_wih_bf16(
    const float* __restrict__ bih, const float* __restrict__ bhh, int d, int layer)
{
    const __nv_bfloat16* X = blockIdx.z ? g_HX : g_PX;
    const __nv_bfloat16* Wb = g_W16 + (size_t)layer*400*LDXP;
    float* Y               = blockIdx.z ? g_GH : g_GP;
    extern __shared__ __align__(16) unsigned char smraw[];
    __nv_bfloat16* SA = (__nv_bfloat16*)smraw;        // [2][128*72]
    __nv_bfloat16* SB = SA + 2*SA_ELEMS;              // [2][64*72]
    uint32_t sa_base = (uint32_t)__cvta_generic_to_shared(SA);
    uint32_t sb_base = (uint32_t)__cvta_generic_to_shared(SB);

    int tid  = threadIdx.x;
    int wid  = tid >> 5, lane = tid & 31;
    int wm   = wid >> 1, wn = wid & 1;
    int m0   = blockIdx.y * 128;
    int n0   = blockIdx.x * 64;
    int lg   = lane >> 2;      // 0..7
    int lk   = lane & 3;       // 0..3

    // ldmatrix per-lane address components (element offsets)
    int a_roff = (wm*32 + (lane & 15)) * SAW + ((lane & 16) ? 8 : 0);
    int b_roff = (wn*32 + (lane & 7) + ((lane & 16) ? 8 : 0)) * SAW + ((lane & 8) ? 8 : 0);

    // per-thread load coordinates
    int arow = tid >> 3, ac16 = tid & 7;           // A: rows tid/8 (+256/8 per rep)
    int brow = tid >> 3;                           // B: same mapping, 2 reps

    float acc[2][4][4];
    #pragma unroll
    for (int i = 0; i < 2; i++)
        #pragma unroll
        for (int j = 0; j < 4; j++)
            #pragma unroll
            for (int r = 0; r < 4; r++) acc[i][j][r] = 0.f;

    int nChunk = (d + 63) >> 6;

    auto issueStage = [&](int st, int k0) {
        uint32_t sa = sa_base + st*SA_ELEMS*2;
        uint32_t sb = sb_base + st*SB_ELEMS*2;
        #pragma unroll
        for (int q = 0; q < 4; q++) {
            int row = arow + q*32;
            int c0  = k0 + ac16*8;
            int nb  = (d - c0)*2;
            nb = nb < 0 ? 0 : (nb > 16 ? 16 : nb);
            int cs  = nb ? c0 : 0;   // keep address in-bounds when nb==0
            cp_async16(sa + (row*SAW + ac16*8)*2,
                       &X[(size_t)(m0+row)*LDXP + cs], nb);
        }
        #pragma unroll
        for (int q = 0; q < 2; q++) {
            int row = brow + q*32;
            int nr  = n0 + row;
            int nb  = (nr < 400) ? 16 : 0;
            int rc  = (nr < 400) ? nr : 0;
            int c0  = k0 + ac16*8;     // W16 zero-padded to LDXP: always in-bounds
            cp_async16(sb + (row*SAW + ac16*8)*2,
                       &Wb[(size_t)rc*LDXP + c0], nb);
        }
        cp_commit();
    };

    issueStage(0, 0);

    for (int kc = 0; kc < nChunk; kc++) {
        int cur = kc & 1;
        bool more = (kc + 1 < nChunk);
        if (more) issueStage(cur ^ 1, (kc+1) << 6);
        if (more) cp_wait<1>(); else cp_wait<0>();
        __syncthreads();

        uint32_t sa_u = sa_base + cur*SA_ELEMS*2;
        uint32_t sb_u = sb_base + cur*SB_ELEMS*2;
        #pragma unroll
        for (int s = 0; s < 4; s++) {
            uint32_t a[2][4], b[4][2];
            #pragma unroll
            for (int mt = 0; mt < 2; mt++)
                ldsm_x4(a[mt][0], a[mt][1], a[mt][2], a[mt][3],
                        sa_u + 2*(a_roff + mt*16*SAW + s*16));
            #pragma unroll
            for (int ntp = 0; ntp < 2; ntp++) {
                uint32_t r0, r1, r2, r3;
                ldsm_x4(r0, r1, r2, r3, sb_u + 2*(b_roff + ntp*16*SAW + s*16));
                b[2*ntp][0] = r0; b[2*ntp][1] = r1;
                b[2*ntp+1][0] = r2; b[2*ntp+1][1] = r3;
            }
            #pragma unroll
            for (int mt = 0; mt < 2; mt++)
                #pragma unroll
                for (int nt = 0; nt < 4; nt++)
                    mma_bf16(acc[mt][nt], a[mt], b[nt]);
        }
        __syncthreads();   // all reads of stage `cur` done before next issue overwrites it
    }

    #pragma unroll
    for (int mt = 0; mt < 2; mt++) {
        int row0 = m0 + wm*32 + mt*16 + lg;
        #pragma unroll
        for (int nt = 0; nt < 4; nt++) {
            int col0 = n0 + wn*32 + nt*8 + 2*lk;
            if (col0 < 400) {
                float bs0 = bih[col0]   + bhh[col0];
                float bs1 = bih[col0+1] + bhh[col0+1];
                Y[(size_t)row0*400 + col0]       = acc[mt][nt][0] + bs0;
                Y[(size_t)row0*400 + col0+1]     = acc[mt][nt][1] + bs1;
                Y[(size_t)(row0+8)*400 + col0]   = acc[mt][nt][2] + bs0;
                Y[(size_t)(row0+8)*400 + col0+1] = acc[mt][nt][3] + bs1;
            }
        }
    }
}

// ------------------------- LSTM recurrence ---------------------------------
// 512 threads, 128 blocks (single wave); block handles (seq, bp) and (seq, bp+64).
// 5-way h split; whh packed as f32x2 pairs (fma.rn.f32x2 = 2 MAC/issue).
__device__ __forceinline__ float sigmf(float x) { return 1.f/(1.f+__expf(-x)); }
__device__ __forceinline__ float tanhf_fast(float x) { return 1.f - 2.f/(__expf(2.f*x)+1.f); }

__global__ __launch_bounds__(512,1) void lstm_kernel(
    const float* __restrict__ whh, int dk, int writeX)
{
    int blk = blockIdx.x;        // 0..127
    int seq = blk >> 6;
    int bp  = blk & 63;
    const float* G = seq ? g_GH : g_GP;
    float* Hout         = seq ? g_HHs : g_PH;
    __nv_bfloat16* Xout = seq ? g_HX  : g_PX;

    int tid  = threadIdx.x;
    int j    = tid % 100;
    int part = tid / 100;        // 0..4 producers; 5 idle tail

    __shared__ __align__(16) float  h_s[2][100];
    __shared__ __align__(16) float4 ps4[2][5][100];

    ull w2[4][10];
    if (part < 5) {
        #pragma unroll
        for (int q = 0; q < 4; q++)
            #pragma unroll
            for (int m = 0; m < 10; m++)
                w2[q][m] = *reinterpret_cast<const ull*>(
                    &whh[(size_t)(q*100 + j)*100 + part*20 + 2*m]);
    }

    int bi = part;               // combiner role for tid<200
    int b  = bi ? bp + 64 : bp;
    float c = 0.f;
    float gr0 = 0.f, gr1 = 0.f, gr2 = 0.f, gr3 = 0.f;
    if (tid < 200) {
        const float* G0 = G + (size_t)b*400;
        gr0 = G0[j]; gr1 = G0[100+j]; gr2 = G0[200+j]; gr3 = G0[300+j];
    }
    if (tid < 100) { h_s[0][tid] = 0.f; h_s[1][tid] = 0.f; }
    __syncthreads();

    for (int t = 0; t < 48; t++) {
        if (part < 5) {
            #pragma unroll
            for (int b2 = 0; b2 < 2; b2++) {
                const ull* hp = reinterpret_cast<const ull*>(&h_s[b2][part*20]);
                ull a0 = 0, a1 = 0, a2 = 0, a3 = 0;
                #pragma unroll
                for (int m = 0; m < 10; m++) {
                    ull h2 = hp[m];
                    fma2(a0, h2, w2[0][m]);
                    fma2(a1, h2, w2[1][m]);
                    fma2(a2, h2, w2[2][m]);
                    fma2(a3, h2, w2[3][m]);
                }
                ps4[b2][part][j] = make_float4(hsum2(a0), hsum2(a1), hsum2(a2), hsum2(a3));
            }
        }
        __syncthreads();
        if (tid < 200) {
            float gi = gr0, gf = gr1, gg = gr2, go = gr3;
            #pragma unroll
            for (int p = 0; p < 5; p++) {
                float4 v = ps4[bi][p][j];
                gi += v.x; gf += v.y; gg += v.z; go += v.w;
            }
            if (t + 1 < 48) {   // prefetch next step's gates
                const float* Gn = G + (size_t)((t+1)*128 + b)*400;
                gr0 = Gn[j]; gr1 = Gn[100+j]; gr2 = Gn[200+j]; gr3 = Gn[300+j];
            }
            c = sigmf(gf)*c + sigmf(gi)*tanhf_fast(gg);
            float h = sigmf(go)*tanhf_fast(c);
            h_s[bi][j] = h;
            Hout[(size_t)(t*128+b)*100 + j] = h;
            if (writeX)
                Xout[(size_t)(t*128+b)*LDXP + dk + 100 + j] = __float2bfloat16(h);
        }
        __syncthreads();
    }
}

// ------------------------- cross attention ---------------------------------
__global__ __launch_bounds__(256) void attn_kernel(int dk)
{
    extern __shared__ __align__(16) float smem[];
    float* hp   = smem;            // 4800
    float* hh   = smem + 4800;     // 4800
    float* attn = smem + 9600;     // 2304
    float* E    = smem + 11904;    // 2304
    float* rmax = smem + 14208;    // 48
    float* rsum = rmax + 48;
    float* cmax = rsum + 48;
    float* csum = cmax + 48;

    int b = blockIdx.x;
    int tid = threadIdx.x;

    for (int idx = tid; idx < 2400; idx += 256) {
        int s = idx / 50, h2 = (idx % 50)*2;
        *reinterpret_cast<float2*>(&hp[s*100+h2]) =
            *reinterpret_cast<const float2*>(&g_PH [(size_t)(s*128+b)*100 + h2]);
        *reinterpret_cast<float2*>(&hh[s*100+h2]) =
            *reinterpret_cast<const float2*>(&g_HHs[(size_t)(s*128+b)*100 + h2]);
    }
    __syncthreads();

    for (int idx = tid; idx < 2304; idx += 256) {
        int p = idx / 48, q = idx % 48;
        const ull* ap = reinterpret_cast<const ull*>(hp + p*100);
        const ull* bq = reinterpret_cast<const ull*>(hh + q*100);
        ull acc = 0;
        #pragma unroll 5
        for (int i = 0; i < 50; i++) fma2(acc, ap[i], bq[i]);
        attn[idx] = hsum2(acc);
    }
    __syncthreads();

    if (tid < 48) {
        float m = -1e30f;
        for (int q = 0; q < 48; q++) m = fmaxf(m, attn[tid*48+q]);
        float s2 = 0.f;
        for (int q = 0; q < 48; q++) s2 += expf(attn[tid*48+q]-m);
        rmax[tid] = m; rsum[tid] = s2;
    } else if (tid >= 128 && tid < 176) {
        int q = tid - 128;
        float m = -1e30f;
        for (int p = 0; p < 48; p++) m = fmaxf(m, attn[p*48+q]);
        float s2 = 0.f;
        for (int p = 0; p < 48; p++) s2 += expf(attn[p*48+q]-m);
        cmax[q] = m; csum[q] = s2;
    }
    __syncthreads();

    for (int idx = tid; idx < 2304; idx += 256) {
        int p = idx / 48;
        E[idx] = expf(attn[idx]-rmax[p]) / rsum[p];
    }
    __syncthreads();
    for (int idx = tid; idx < 2400; idx += 256) {   // a_p
        int p = idx / 50, h2p = idx % 50;
        const ull* hh2 = reinterpret_cast<const ull*>(hh) + h2p;
        ull acc = 0;
        #pragma unroll 4
        for (int q = 0; q < 48; q++) fma2(acc, bcast2(E[p*48+q]), hh2[q*50]);
        float2 r = *reinterpret_cast<float2*>(&acc);
        *reinterpret_cast<__nv_bfloat162*>(&g_PX[(size_t)(p*128+b)*LDXP + dk + 2*h2p]) =
            __float22bfloat162_rn(r);
    }
    __syncthreads();

    for (int idx = tid; idx < 2304; idx += 256) {
        int q = idx % 48;
        E[idx] = expf(attn[idx]-cmax[q]) / csum[q];
    }
    __syncthreads();
    for (int idx = tid; idx < 2400; idx += 256) {   // a_h
        int q = idx / 50, h2p = idx % 50;
        const ull* hp2 = reinterpret_cast<const ull*>(hp) + h2p;
        ull acc = 0;
        #pragma unroll 4
        for (int p = 0; p < 48; p++) fma2(acc, bcast2(E[p*48+q]), hp2[p*50]);
        float2 r = *reinterpret_cast<float2*>(&acc);
        *reinterpret_cast<__nv_bfloat162*>(&g_HX[(size_t)(q*128+b)*LDXP + dk + 2*h2p]) =
            __float22bfloat162_rn(r);
    }
}

// ------------------------- pooling + FC head -------------------------------
__global__ __launch_bounds__(256) void head_kernel(
    const float* __restrict__ fcl_w, const float* __restrict__ fcl_b,
    const float* __restrict__ last_w, const float* __restrict__ last_b,
    float* __restrict__ out)
{
    __shared__ __align__(16) float feats[500];
    __shared__ float o1[800];
    __shared__ float red[256];
    int b = blockIdx.x, tid = threadIdx.x;

    if (tid < 100) {
        float hq = -1e30f, hs = -1e30f;
        for (int s = 0; s < 48; s++) {
            hq = fmaxf(hq, g_PH [(size_t)(s*128+b)*100 + tid]);
            hs = fmaxf(hs, g_HHs[(size_t)(s*128+b)*100 + tid]);
        }
        feats[tid]       = hq;
        feats[100 + tid] = hs;
        feats[200 + tid] = hs - hq;
        feats[300 + tid] = hq * hs;
        feats[400 + tid] = fabsf(hq - hs);
    }
    __syncthreads();

    for (int o = tid; o < 800; o += 256) {
        const ull* f2 = reinterpret_cast<const ull*>(feats);
        const ull* w2 = reinterpret_cast<const ull*>(fcl_w + (size_t)o*500);
        ull acc = 0;
        #pragma unroll 5
        for (int k = 0; k < 250; k++) fma2(acc, f2[k], w2[k]);
        o1[o] = fmaxf(hsum2(acc) + fcl_b[o], 0.f);
    }
    __syncthreads();

    for (int cc = 0; cc < 2; cc++) {
        float pa = 0.f;
        for (int o = tid; o < 800; o += 256) pa += o1[o]*last_w[cc*800+o];
        red[tid] = pa;
        __syncthreads();
        for (int off = 128; off; off >>= 1) {
            if (tid < off) red[tid] += red[tid+off];
            __syncthreads();
        }
        if (tid == 0) {
            float v = red[0] + last_b[cc];
            out[b*2+cc] = 1.f/(1.f+expf(-v));
        }
        __syncthreads();
    }
}

// ------------------------- launch ------------------------------------------
extern "C" void kernel_launch(void* const* d_in, const int* in_sizes, int n_in,
                              void* d_out, int out_size)
{
    const int*   q_words  = (const int*)d_in[0];
    const int*   q_chars  = (const int*)d_in[1];
    const int*   s_words  = (const int*)d_in[2];
    const int*   s_chars  = (const int*)d_in[3];
    const float* word_emb = (const float*)d_in[4];
    const float* char_emb = (const float*)d_in[5];
    const float* conv_w   = (const float*)d_in[6];
    const float* conv_b   = (const float*)d_in[7];
    const float* fcl_w    = (const float*)d_in[28];
    const float* fcl_b    = (const float*)d_in[29];
    const float* last_w   = (const float*)d_in[30];
    const float* last_b   = (const float*)d_in[31];
    float* out = (float*)d_out;

    const int gemm_smem = 2*(SA_ELEMS + SB_ELEMS)*2;   // 55296 bytes
    cudaFuncSetAttribute(gemm_wih_bf16, cudaFuncAttributeMaxDynamicSharedMemorySize, gemm_smem);
    cudaFuncSetAttribute(attn_kernel, cudaFuncAttributeMaxDynamicSharedMemorySize, 57600);

    // weight conversion for ALL layers up front (off the serial critical path)
    convert_w_all<<<2000,128>>>((const float*)d_in[8],  (const float*)d_in[12],
                                (const float*)d_in[16], (const float*)d_in[20],
                                (const float*)d_in[24]);

    dim3 ge(6144, 2);
    embed_kernel<<<ge,128>>>(q_words, q_chars, s_words, s_chars,
                             word_emb, char_emb, conv_w, conv_b);

    const int dims[5] = {316, 516, 716, 916, 1116};
    for (int k = 0; k < 5; k++) {
        const float* whh = (const float*)d_in[9+4*k];
        const float* bih = (const float*)d_in[10+4*k];
        const float* bhh = (const float*)d_in[11+4*k];
        dim3 gg(7, 48, 2);
        gemm_wih_bf16<<<gg, 256, gemm_smem>>>(bih, bhh, dims[k], k);
        lstm_kernel<<<128, 512>>>(whh, dims[k], (k < 4) ? 1 : 0);
        if (k < 4) attn_kernel<<<128, 256, 57600>>>(dims[k]);
    }
    head_kernel<<<128, 256>>>(fcl_w, fcl_b, last_w, last_b, out);
}